// round 11
// baseline (speedup 1.0000x reference)
#include <cuda_runtime.h>
#include <cuda_bf16.h>
#include <cstdint>

// Problem constants
#define NV     100000
#define DIN    512
#define DOUT   512
#define NC     4096
#define KPC    32      // vars per cluster
#define NE     16384   // edges
#define NS     16      // shared vars per edge
#define NEG_SLOPE 0.2f
#define CAP    64      // max edge contributions tracked per variable

// Scratch (device globals; no allocation allowed)
__device__ float          g_feats[NC * DIN];   // 8 MB
__device__ float          g_G[NC * DOUT];      // 8 MB  (G = F * Mt^T)
__device__ __nv_bfloat16  g_Vh[NC * DOUT];     // 4 MB  (bf16 V for gather)
__device__ float          g_Mt[DIN * DOUT];    // 1 MB  (Mt[j][i] = (Wq^T Wk)[i][j])
__device__ float          g_attn[NE];          // 64 KB
__device__ int            g_count[NV];         // zero-init; gather re-zeros
__device__ int            g_list[(size_t)NV * CAP]; // 25.6 MB

__device__ __forceinline__ uint32_t f32_to_tf32(float f)
{
    uint32_t u;
    asm("cvt.rna.tf32.f32 %0, %1;" : "=r"(u) : "f"(f));
    return u;
}

__device__ __forceinline__ void mma_tf32(
    float& d0, float& d1, float& d2, float& d3,
    uint32_t a0, uint32_t a1, uint32_t a2, uint32_t a3,
    uint32_t b0, uint32_t b1)
{
    asm volatile(
        "mma.sync.aligned.m16n8k8.row.col.f32.tf32.tf32.f32 "
        "{%0,%1,%2,%3}, {%4,%5,%6,%7}, {%8,%9}, {%0,%1,%2,%3};"
        : "+f"(d0), "+f"(d1), "+f"(d2), "+f"(d3)
        : "r"(a0), "r"(a1), "r"(a2), "r"(a3), "r"(b0), "r"(b1));
}

// ===========================================================================
// Kernel 0: Mt = Wk^T * Wq  (Mt[m][n] = sum_d Wk[d][m] * Wq[d][n])
// 64x64 tiles, grid 8x8 = 64 CTAs, 128 thr = 4 warps (2x2), warp tile 32x32.
// Transposed staging: lanes vary k -> conflict-free smem stores; strided
// global reads (one sector/lane) hit L2 after first chunk (Wk/Wq are 1MB).
// ===========================================================================
#define SSTRIDE 36

__global__ __launch_bounds__(128) void mm_small_kernel(
    const float* __restrict__ Wk, const float* __restrict__ Wq)
{
    __shared__ uint32_t As[64 * SSTRIDE];
    __shared__ uint32_t Bs[64 * SSTRIDE];

    const int tid  = threadIdx.x;
    const int wid  = tid >> 5;
    const int lane = tid & 31;
    const int bm = blockIdx.y * 64;
    const int bn = blockIdx.x * 64;

    const int warp_m = (wid >> 1) * 32;   // 0 or 32
    const int warp_n = (wid & 1) * 32;    // 0 or 32
    const int lr = lane >> 2;             // 0..7
    const int lc = lane & 3;              // 0..3

    float acc[2][4][4];
#pragma unroll
    for (int i = 0; i < 2; i++)
#pragma unroll
        for (int j = 0; j < 4; j++)
#pragma unroll
            for (int r = 0; r < 4; r++) acc[i][j][r] = 0.f;

    for (int k0 = 0; k0 < DIN; k0 += 32) {
        // stage transposed: As[m][k] = Wk[k0+k][bm+m]
#pragma unroll
        for (int i = 0; i < 4; i++) {
            const int q  = tid + i * 128;   // 0..511
            const int k  = q & 31;          // = lane
            const int iq = q >> 5;          // 0..15
            const float4 a = *reinterpret_cast<const float4*>(
                Wk + (size_t)(k0 + k) * DIN + bm + iq * 4);
            As[(iq * 4 + 0) * SSTRIDE + k] = f32_to_tf32(a.x);
            As[(iq * 4 + 1) * SSTRIDE + k] = f32_to_tf32(a.y);
            As[(iq * 4 + 2) * SSTRIDE + k] = f32_to_tf32(a.z);
            As[(iq * 4 + 3) * SSTRIDE + k] = f32_to_tf32(a.w);
            const float4 b = *reinterpret_cast<const float4*>(
                Wq + (size_t)(k0 + k) * DIN + bn + iq * 4);
            Bs[(iq * 4 + 0) * SSTRIDE + k] = f32_to_tf32(b.x);
            Bs[(iq * 4 + 1) * SSTRIDE + k] = f32_to_tf32(b.y);
            Bs[(iq * 4 + 2) * SSTRIDE + k] = f32_to_tf32(b.z);
            Bs[(iq * 4 + 3) * SSTRIDE + k] = f32_to_tf32(b.w);
        }
        __syncthreads();

#pragma unroll
        for (int ks = 0; ks < 4; ks++) {
            const int kk = ks * 8;
            uint32_t af[2][4];
#pragma unroll
            for (int mf = 0; mf < 2; mf++) {
                const int rbase = (warp_m + mf * 16 + lr) * SSTRIDE + kk + lc;
                af[mf][0] = As[rbase];
                af[mf][1] = As[rbase + 8 * SSTRIDE];
                af[mf][2] = As[rbase + 4];
                af[mf][3] = As[rbase + 8 * SSTRIDE + 4];
            }
            uint32_t bf[4][2];
#pragma unroll
            for (int nf = 0; nf < 4; nf++) {
                const int rbase = (warp_n + nf * 8 + lr) * SSTRIDE + kk + lc;
                bf[nf][0] = Bs[rbase];
                bf[nf][1] = Bs[rbase + 4];
            }
#pragma unroll
            for (int mf = 0; mf < 2; mf++)
#pragma unroll
                for (int nf = 0; nf < 4; nf++)
                    mma_tf32(acc[mf][nf][0], acc[mf][nf][1],
                             acc[mf][nf][2], acc[mf][nf][3],
                             af[mf][0], af[mf][1], af[mf][2], af[mf][3],
                             bf[nf][0], bf[nf][1]);
        }
        __syncthreads();
    }

#pragma unroll
    for (int mf = 0; mf < 2; mf++) {
#pragma unroll
        for (int nf = 0; nf < 4; nf++) {
            const int row = bm + warp_m + mf * 16 + lr;
            const int col = bn + warp_n + nf * 8 + lc * 2;
            float2 v0 = make_float2(acc[mf][nf][0], acc[mf][nf][1]);
            float2 v1 = make_float2(acc[mf][nf][2], acc[mf][nf][3]);
            *reinterpret_cast<float2*>(g_Mt + (size_t)row * DOUT + col) = v0;
            *reinterpret_cast<float2*>(g_Mt + (size_t)(row + 8) * DOUT + col) = v1;
        }
    }
}

// ===========================================================================
// Kernel 1: per-cluster mean pooling (at DRAM roofline)
// ===========================================================================
__global__ __launch_bounds__(128) void pool_kernel(
    const float* __restrict__ x, const int* __restrict__ ids)
{
    const int c = blockIdx.x;
    const int t = threadIdx.x;
    __shared__ int s_ids[KPC];
    if (t < KPC) s_ids[t] = ids[c * KPC + t];
    __syncthreads();

    float4 acc = make_float4(0.f, 0.f, 0.f, 0.f);
#pragma unroll 4
    for (int k = 0; k < KPC; k++) {
        const float4 v = reinterpret_cast<const float4*>(
            x + (size_t)s_ids[k] * DIN)[t];
        acc.x += v.x; acc.y += v.y; acc.z += v.z; acc.w += v.w;
    }
    const float inv = 1.0f / (float)KPC;
    acc.x *= inv; acc.y *= inv; acc.z *= inv; acc.w *= inv;
    reinterpret_cast<float4*>(g_feats + (size_t)c * DIN)[t] = acc;
}

// ===========================================================================
// Kernel 2: main tf32 GEMM, 2 z-slices (256 CTAs -> balanced single wave).
// z==0: G = F * Mt^T   (fp32 out to g_G)
// z==1: V = F * Wv^T   (bf16 out to g_Vh)
// CTA tile 128x128x32, 128 thr = 4 warps (2x2), warp tile 64x64.
// ===========================================================================
#define BM 128
#define BN 128
#define BK 32

__global__ __launch_bounds__(128) void gemm_tc_kernel(
    const float* __restrict__ WV)
{
    __shared__ uint32_t As[BM * SSTRIDE];
    __shared__ uint32_t Bs[BN * SSTRIDE];

    const float* Bsrc = (blockIdx.z == 0) ? g_Mt : WV;
    const float* A = g_feats;

    const int tid  = threadIdx.x;
    const int wid  = tid >> 5;
    const int lane = tid & 31;
    const int bm = blockIdx.y * BM;
    const int bn = blockIdx.x * BN;

    const int warp_m = (wid >> 1) * 64;   // 0 or 64
    const int warp_n = (wid & 1) * 64;    // 0 or 64
    const int lr = lane >> 2;             // 0..7
    const int lc = lane & 3;              // 0..3

    float acc[4][8][4];
#pragma unroll
    for (int i = 0; i < 4; i++)
#pragma unroll
        for (int j = 0; j < 8; j++)
#pragma unroll
            for (int r = 0; r < 4; r++) acc[i][j][r] = 0.f;

    for (int k0 = 0; k0 < DIN; k0 += BK) {
#pragma unroll
        for (int i = 0; i < 8; i++) {
            const int q   = tid + i * 128;     // 0..1023 float4 slots
            const int row = q >> 3;            // 0..127
            const int kq  = (q & 7) * 4;       // 0..28
            const float4 a = *reinterpret_cast<const float4*>(
                A + (size_t)(bm + row) * DIN + k0 + kq);
            uint4 ua;
            ua.x = f32_to_tf32(a.x); ua.y = f32_to_tf32(a.y);
            ua.z = f32_to_tf32(a.z); ua.w = f32_to_tf32(a.w);
            *reinterpret_cast<uint4*>(&As[row * SSTRIDE + kq]) = ua;
            const float4 b = *reinterpret_cast<const float4*>(
                Bsrc + (size_t)(bn + row) * DIN + k0 + kq);
            uint4 ub;
            ub.x = f32_to_tf32(b.x); ub.y = f32_to_tf32(b.y);
            ub.z = f32_to_tf32(b.z); ub.w = f32_to_tf32(b.w);
            *reinterpret_cast<uint4*>(&Bs[row * SSTRIDE + kq]) = ub;
        }
        __syncthreads();

#pragma unroll
        for (int ks = 0; ks < 4; ks++) {
            const int kk = ks * 8;
            uint32_t af[4][4];
#pragma unroll
            for (int mf = 0; mf < 4; mf++) {
                const int rbase = (warp_m + mf * 16 + lr) * SSTRIDE + kk + lc;
                af[mf][0] = As[rbase];
                af[mf][1] = As[rbase + 8 * SSTRIDE];
                af[mf][2] = As[rbase + 4];
                af[mf][3] = As[rbase + 8 * SSTRIDE + 4];
            }
            uint32_t bf[8][2];
#pragma unroll
            for (int nf = 0; nf < 8; nf++) {
                const int rbase = (warp_n + nf * 8 + lr) * SSTRIDE + kk + lc;
                bf[nf][0] = Bs[rbase];
                bf[nf][1] = Bs[rbase + 4];
            }
#pragma unroll
            for (int mf = 0; mf < 4; mf++)
#pragma unroll
                for (int nf = 0; nf < 8; nf++)
                    mma_tf32(acc[mf][nf][0], acc[mf][nf][1],
                             acc[mf][nf][2], acc[mf][nf][3],
                             af[mf][0], af[mf][1], af[mf][2], af[mf][3],
                             bf[nf][0], bf[nf][1]);
        }
        __syncthreads();
    }

    // epilogue
    if (blockIdx.z == 0) {
#pragma unroll
        for (int mf = 0; mf < 4; mf++) {
#pragma unroll
            for (int nf = 0; nf < 8; nf++) {
                const int row = bm + warp_m + mf * 16 + lr;
                const int col = bn + warp_n + nf * 8 + lc * 2;
                float2 v0 = make_float2(acc[mf][nf][0], acc[mf][nf][1]);
                float2 v1 = make_float2(acc[mf][nf][2], acc[mf][nf][3]);
                *reinterpret_cast<float2*>(g_G + (size_t)row * DOUT + col) = v0;
                *reinterpret_cast<float2*>(g_G + (size_t)(row + 8) * DOUT + col) = v1;
            }
        }
    } else {
#pragma unroll
        for (int mf = 0; mf < 4; mf++) {
#pragma unroll
            for (int nf = 0; nf < 8; nf++) {
                const int row = bm + warp_m + mf * 16 + lr;
                const int col = bn + warp_n + nf * 8 + lc * 2;
                const __nv_bfloat162 h0 = __float22bfloat162_rn(
                    make_float2(acc[mf][nf][0], acc[mf][nf][1]));
                const __nv_bfloat162 h1 = __float22bfloat162_rn(
                    make_float2(acc[mf][nf][2], acc[mf][nf][3]));
                *reinterpret_cast<__nv_bfloat162*>(
                    g_Vh + (size_t)row * DOUT + col) = h0;
                *reinterpret_cast<__nv_bfloat162*>(
                    g_Vh + (size_t)(row + 8) * DOUT + col) = h1;
            }
        }
    }
}

// ===========================================================================
// Kernel 3: fused attn scores + incidence-list build.
// score = G[c1] . F[c2]  (== Q[c1].K[c2] algebraically)
// Blocks [0, 2048): one warp per edge.  [2048, 3072): list build.
// ===========================================================================
#define ATTN_BLOCKS ((NE * 32) / 256)            // 2048
#define BUILD_BLOCKS ((NE * NS + 255) / 256)     // 1024

__global__ __launch_bounds__(256) void attn_build_kernel(
    const int* __restrict__ edge_index,
    const float* __restrict__ head_weights,
    const int* __restrict__ active_heads,
    const int* __restrict__ shared_vars)
{
    if (blockIdx.x >= ATTN_BLOCKS) {
        const int idx = (blockIdx.x - ATTN_BLOCKS) * 256 + threadIdx.x;
        if (idx < NE * NS) {
            const int v = shared_vars[idx];
            const int e = idx >> 4;          // NS = 16
            const int pos = atomicAdd(&g_count[v], 1);
            if (pos < CAP) g_list[(size_t)v * CAP + pos] = e;
        }
        return;
    }

    const int e = (blockIdx.x * 256 + threadIdx.x) >> 5;
    const int lane = threadIdx.x & 31;

    const int c1 = edge_index[e];
    const int c2 = edge_index[NE + e];
    const float4* Q4 = reinterpret_cast<const float4*>(g_G + (size_t)c1 * DOUT);
    const float4* K4 = reinterpret_cast<const float4*>(g_feats + (size_t)c2 * DIN);

    float p = 0.f;
#pragma unroll
    for (int j = 0; j < 4; j++) {
        const float4 q = Q4[lane + 32 * j];
        const float4 k = K4[lane + 32 * j];
        p += q.x * k.x + q.y * k.y + q.z * k.z + q.w * k.w;
    }
#pragma unroll
    for (int off = 16; off > 0; off >>= 1)
        p += __shfl_xor_sync(0xFFFFFFFFu, p, off);

    if (lane == 0) {
        float s = p * rsqrtf((float)DOUT);
        s = (s >= 0.f) ? s : NEG_SLOPE * s;
        const float sig = 1.0f / (1.0f + __expf(-s));
        const int ah = active_heads[0];
        float hm = 0.f;
        for (int i = 0; i < ah; i++) hm += head_weights[i];
        hm /= (float)ah;
        g_attn[e] = sig * hm;
    }
}

// ===========================================================================
// Kernel 4: gather. x_out[v] = x_var[v] + sum attn[e] * Vh[c2[e]]  (bf16 V)
// ===========================================================================
__global__ __launch_bounds__(128) void gather_kernel(
    const float* __restrict__ x,
    const int* __restrict__ edge_index,
    float* __restrict__ x_out)
{
    const int v = blockIdx.x;
    const int t = threadIdx.x;

    const float4 xrow = __ldcs(
        reinterpret_cast<const float4*>(x + (size_t)v * DIN) + t);

    int cnt = g_count[v];
    if (cnt > CAP) cnt = CAP;

    __shared__ float s_a[CAP];
    __shared__ int   s_c[CAP];
    if (t < cnt) {
        const int e = g_list[(size_t)v * CAP + t];
        s_a[t] = g_attn[e];
        s_c[t] = edge_index[NE + e];
    }
    __syncthreads();
    if (t == 0) g_count[v] = 0;   // reset for next launch

    float4 acc0 = xrow;
    float4 acc1 = make_float4(0.f, 0.f, 0.f, 0.f);

    int i = 0;
    for (; i + 2 <= cnt; i += 2) {
        const float a0 = s_a[i];
        const float a1 = s_a[i + 1];
        const uint2 r0 = *reinterpret_cast<const uint2*>(
            g_Vh + (size_t)s_c[i] * DOUT + t * 4);
        const uint2 r1 = *reinterpret_cast<const uint2*>(
            g_Vh + (size_t)s_c[i + 1] * DOUT + t * 4);
        const float2 w0a = __bfloat1622float2(
            *reinterpret_cast<const __nv_bfloat162*>(&r0.x));
        const float2 w0b = __bfloat1622float2(
            *reinterpret_cast<const __nv_bfloat162*>(&r0.y));
        const float2 w1a = __bfloat1622float2(
            *reinterpret_cast<const __nv_bfloat162*>(&r1.x));
        const float2 w1b = __bfloat1622float2(
            *reinterpret_cast<const __nv_bfloat162*>(&r1.y));
        acc0.x += a0 * w0a.x; acc0.y += a0 * w0a.y;
        acc0.z += a0 * w0b.x; acc0.w += a0 * w0b.y;
        acc1.x += a1 * w1a.x; acc1.y += a1 * w1a.y;
        acc1.z += a1 * w1b.x; acc1.w += a1 * w1b.y;
    }
    if (i < cnt) {
        const float a0 = s_a[i];
        const uint2 r0 = *reinterpret_cast<const uint2*>(
            g_Vh + (size_t)s_c[i] * DOUT + t * 4);
        const float2 w0a = __bfloat1622float2(
            *reinterpret_cast<const __nv_bfloat162*>(&r0.x));
        const float2 w0b = __bfloat1622float2(
            *reinterpret_cast<const __nv_bfloat162*>(&r0.y));
        acc0.x += a0 * w0a.x; acc0.y += a0 * w0a.y;
        acc0.z += a0 * w0b.x; acc0.w += a0 * w0b.y;
    }
    acc0.x += acc1.x; acc0.y += acc1.y;
    acc0.z += acc1.z; acc0.w += acc1.w;

    __stcs(reinterpret_cast<float4*>(x_out + (size_t)v * DIN) + t, acc0);
}

// ===========================================================================
// Launch — single stream, linear graph, 5 kernels
// ===========================================================================
extern "C" void kernel_launch(void* const* d_in, const int* in_sizes, int n_in,
                              void* d_out, int out_size)
{
    const float* x_var        = (const float*)d_in[0];
    const float* W_Q          = (const float*)d_in[1];
    const float* W_K          = (const float*)d_in[2];
    const float* W_V          = (const float*)d_in[3];
    const float* head_weights = (const float*)d_in[4];
    const int*   cluster_ids  = (const int*)d_in[5];
    const int*   edge_index   = (const int*)d_in[6];
    const int*   shared_vars  = (const int*)d_in[7];
    const int*   active_heads = (const int*)d_in[8];
    float*       x_out        = (float*)d_out;

    // Mt = Wk^T * Wq  (tiny; independent of pool)
    dim3 mgrid(DOUT / 64, DIN / 64);
    mm_small_kernel<<<mgrid, 128>>>(W_K, W_Q);

    pool_kernel<<<NC, 128>>>(x_var, cluster_ids);

    dim3 ggrid(DOUT / BN, NC / BM, 2);
    gemm_tc_kernel<<<ggrid, 128>>>(W_V);

    attn_build_kernel<<<ATTN_BLOCKS + BUILD_BLOCKS, 256>>>(
        edge_index, head_weights, active_heads, shared_vars);

    gather_kernel<<<NV, 128>>>(x_var, edge_index, x_out);
}

// round 12
// speedup vs baseline: 1.0069x; 1.0069x over previous
#include <cuda_runtime.h>
#include <cuda_bf16.h>
#include <cstdint>

// Problem constants
#define NV     100000
#define DIN    512
#define DOUT   512
#define NC     4096
#define KPC    32      // vars per cluster
#define NE     16384   // edges
#define NS     16      // shared vars per edge
#define NEG_SLOPE 0.2f
#define CAP    64      // max edge contributions tracked per variable

// Scratch (device globals; no allocation allowed)
__device__ float          g_feats[NC * DIN];   // 8 MB
__device__ float          g_G[NC * DOUT];      // 8 MB  (G = F * Mt^T)
__device__ __nv_bfloat16  g_Vh[NC * DOUT];     // 4 MB  (bf16 V for gather)
__device__ float          g_Mt[DIN * DOUT];    // 1 MB  (Mt[n][k] = sum_i Wk[i][n] Wq[i][k])
__device__ float          g_attn[NE];          // 64 KB
__device__ int            g_count[NV];         // zero-init; gather re-zeros
__device__ int            g_list[(size_t)NV * CAP]; // 25.6 MB

__device__ __forceinline__ uint32_t f32_to_tf32(float f)
{
    uint32_t u;
    asm("cvt.rna.tf32.f32 %0, %1;" : "=r"(u) : "f"(f));
    return u;
}

__device__ __forceinline__ void mma_tf32(
    float& d0, float& d1, float& d2, float& d3,
    uint32_t a0, uint32_t a1, uint32_t a2, uint32_t a3,
    uint32_t b0, uint32_t b1)
{
    asm volatile(
        "mma.sync.aligned.m16n8k8.row.col.f32.tf32.tf32.f32 "
        "{%0,%1,%2,%3}, {%4,%5,%6,%7}, {%8,%9}, {%0,%1,%2,%3};"
        : "+f"(d0), "+f"(d1), "+f"(d2), "+f"(d3)
        : "r"(a0), "r"(a1), "r"(a2), "r"(a3), "r"(b0), "r"(b1));
}

// ===========================================================================
// Kernel 0: Mt = Wk^T * Wq  (Mt[m][n] = sum_i Wk[i][bm+m] * Wq[i][bn+n])
// 64x64 tiles, grid 8x8 = 64 CTAs, 128 thr = 4 warps (2x2), warp tile 32x32.
// COALESCED staging (R12 fix): half-warps read 64B runs along the output
// dim; transposed smem stores (bank conflicts are negligible vs the 32-way
// sector split the old lane-varies-k mapping caused).
// ===========================================================================
#define SSTRIDE 36

__global__ __launch_bounds__(128) void mm_small_kernel(
    const float* __restrict__ Wk, const float* __restrict__ Wq)
{
    __shared__ uint32_t As[64 * SSTRIDE];
    __shared__ uint32_t Bs[64 * SSTRIDE];

    const int tid  = threadIdx.x;
    const int wid  = tid >> 5;
    const int lane = tid & 31;
    const int bm = blockIdx.y * 64;
    const int bn = blockIdx.x * 64;

    const int warp_m = (wid >> 1) * 32;   // 0 or 32
    const int warp_n = (wid & 1) * 32;    // 0 or 32
    const int lr = lane >> 2;             // 0..7
    const int lc = lane & 3;              // 0..3

    float acc[2][4][4];
#pragma unroll
    for (int i = 0; i < 2; i++)
#pragma unroll
        for (int j = 0; j < 4; j++)
#pragma unroll
            for (int r = 0; r < 4; r++) acc[i][j][r] = 0.f;

    for (int i0 = 0; i0 < DIN; i0 += 32) {
        // stage transposed, coalesced reads: As[m][ii] = Wk[i0+ii][bm+m]
#pragma unroll
        for (int it = 0; it < 4; it++) {
            const int q  = tid + it * 128;  // 0..511
            const int ii = q >> 4;          // 0..31 (contraction index)
            const int mq = (q & 15) * 4;    // 0..60 (output-dim offset)
            const float4 a = *reinterpret_cast<const float4*>(
                Wk + (size_t)(i0 + ii) * DIN + bm + mq);
            As[(mq + 0) * SSTRIDE + ii] = f32_to_tf32(a.x);
            As[(mq + 1) * SSTRIDE + ii] = f32_to_tf32(a.y);
            As[(mq + 2) * SSTRIDE + ii] = f32_to_tf32(a.z);
            As[(mq + 3) * SSTRIDE + ii] = f32_to_tf32(a.w);
            const float4 b = *reinterpret_cast<const float4*>(
                Wq + (size_t)(i0 + ii) * DIN + bn + mq);
            Bs[(mq + 0) * SSTRIDE + ii] = f32_to_tf32(b.x);
            Bs[(mq + 1) * SSTRIDE + ii] = f32_to_tf32(b.y);
            Bs[(mq + 2) * SSTRIDE + ii] = f32_to_tf32(b.z);
            Bs[(mq + 3) * SSTRIDE + ii] = f32_to_tf32(b.w);
        }
        __syncthreads();

#pragma unroll
        for (int ks = 0; ks < 4; ks++) {
            const int kk = ks * 8;
            uint32_t af[2][4];
#pragma unroll
            for (int mf = 0; mf < 2; mf++) {
                const int rbase = (warp_m + mf * 16 + lr) * SSTRIDE + kk + lc;
                af[mf][0] = As[rbase];
                af[mf][1] = As[rbase + 8 * SSTRIDE];
                af[mf][2] = As[rbase + 4];
                af[mf][3] = As[rbase + 8 * SSTRIDE + 4];
            }
            uint32_t bf[4][2];
#pragma unroll
            for (int nf = 0; nf < 4; nf++) {
                const int rbase = (warp_n + nf * 8 + lr) * SSTRIDE + kk + lc;
                bf[nf][0] = Bs[rbase];
                bf[nf][1] = Bs[rbase + 4];
            }
#pragma unroll
            for (int mf = 0; mf < 2; mf++)
#pragma unroll
                for (int nf = 0; nf < 4; nf++)
                    mma_tf32(acc[mf][nf][0], acc[mf][nf][1],
                             acc[mf][nf][2], acc[mf][nf][3],
                             af[mf][0], af[mf][1], af[mf][2], af[mf][3],
                             bf[nf][0], bf[nf][1]);
        }
        __syncthreads();
    }

#pragma unroll
    for (int mf = 0; mf < 2; mf++) {
#pragma unroll
        for (int nf = 0; nf < 4; nf++) {
            const int row = bm + warp_m + mf * 16 + lr;
            const int col = bn + warp_n + nf * 8 + lc * 2;
            float2 v0 = make_float2(acc[mf][nf][0], acc[mf][nf][1]);
            float2 v1 = make_float2(acc[mf][nf][2], acc[mf][nf][3]);
            *reinterpret_cast<float2*>(g_Mt + (size_t)row * DOUT + col) = v0;
            *reinterpret_cast<float2*>(g_Mt + (size_t)(row + 8) * DOUT + col) = v1;
        }
    }
}

// ===========================================================================
// Kernel 1: per-cluster mean pooling (at DRAM roofline)
// ===========================================================================
__global__ __launch_bounds__(128) void pool_kernel(
    const float* __restrict__ x, const int* __restrict__ ids)
{
    const int c = blockIdx.x;
    const int t = threadIdx.x;
    __shared__ int s_ids[KPC];
    if (t < KPC) s_ids[t] = ids[c * KPC + t];
    __syncthreads();

    float4 acc = make_float4(0.f, 0.f, 0.f, 0.f);
#pragma unroll 4
    for (int k = 0; k < KPC; k++) {
        const float4 v = reinterpret_cast<const float4*>(
            x + (size_t)s_ids[k] * DIN)[t];
        acc.x += v.x; acc.y += v.y; acc.z += v.z; acc.w += v.w;
    }
    const float inv = 1.0f / (float)KPC;
    acc.x *= inv; acc.y *= inv; acc.z *= inv; acc.w *= inv;
    reinterpret_cast<float4*>(g_feats + (size_t)c * DIN)[t] = acc;
}

// ===========================================================================
// Kernel 2: main tf32 GEMM, 2 z-slices (256 CTAs -> balanced wave).
// z==0: G = F * Mt^T   (fp32 out to g_G)
// z==1: V = F * Wv^T   (bf16 out to g_Vh)
// CTA tile 128x128x32, 128 thr = 4 warps (2x2), warp tile 64x64.
// ===========================================================================
#define BM 128
#define BN 128
#define BK 32

__global__ __launch_bounds__(128) void gemm_tc_kernel(
    const float* __restrict__ WV)
{
    __shared__ uint32_t As[BM * SSTRIDE];
    __shared__ uint32_t Bs[BN * SSTRIDE];

    const float* Bsrc = (blockIdx.z == 0) ? g_Mt : WV;
    const float* A = g_feats;

    const int tid  = threadIdx.x;
    const int wid  = tid >> 5;
    const int lane = tid & 31;
    const int bm = blockIdx.y * BM;
    const int bn = blockIdx.x * BN;

    const int warp_m = (wid >> 1) * 64;   // 0 or 64
    const int warp_n = (wid & 1) * 64;    // 0 or 64
    const int lr = lane >> 2;             // 0..7
    const int lc = lane & 3;              // 0..3

    float acc[4][8][4];
#pragma unroll
    for (int i = 0; i < 4; i++)
#pragma unroll
        for (int j = 0; j < 8; j++)
#pragma unroll
            for (int r = 0; r < 4; r++) acc[i][j][r] = 0.f;

    for (int k0 = 0; k0 < DIN; k0 += BK) {
#pragma unroll
        for (int i = 0; i < 8; i++) {
            const int q   = tid + i * 128;     // 0..1023 float4 slots
            const int row = q >> 3;            // 0..127
            const int kq  = (q & 7) * 4;       // 0..28
            const float4 a = *reinterpret_cast<const float4*>(
                A + (size_t)(bm + row) * DIN + k0 + kq);
            uint4 ua;
            ua.x = f32_to_tf32(a.x); ua.y = f32_to_tf32(a.y);
            ua.z = f32_to_tf32(a.z); ua.w = f32_to_tf32(a.w);
            *reinterpret_cast<uint4*>(&As[row * SSTRIDE + kq]) = ua;
            const float4 b = *reinterpret_cast<const float4*>(
                Bsrc + (size_t)(bn + row) * DIN + k0 + kq);
            uint4 ub;
            ub.x = f32_to_tf32(b.x); ub.y = f32_to_tf32(b.y);
            ub.z = f32_to_tf32(b.z); ub.w = f32_to_tf32(b.w);
            *reinterpret_cast<uint4*>(&Bs[row * SSTRIDE + kq]) = ub;
        }
        __syncthreads();

#pragma unroll
        for (int ks = 0; ks < 4; ks++) {
            const int kk = ks * 8;
            uint32_t af[4][4];
#pragma unroll
            for (int mf = 0; mf < 4; mf++) {
                const int rbase = (warp_m + mf * 16 + lr) * SSTRIDE + kk + lc;
                af[mf][0] = As[rbase];
                af[mf][1] = As[rbase + 8 * SSTRIDE];
                af[mf][2] = As[rbase + 4];
                af[mf][3] = As[rbase + 8 * SSTRIDE + 4];
            }
            uint32_t bf[8][2];
#pragma unroll
            for (int nf = 0; nf < 8; nf++) {
                const int rbase = (warp_n + nf * 8 + lr) * SSTRIDE + kk + lc;
                bf[nf][0] = Bs[rbase];
                bf[nf][1] = Bs[rbase + 4];
            }
#pragma unroll
            for (int mf = 0; mf < 4; mf++)
#pragma unroll
                for (int nf = 0; nf < 8; nf++)
                    mma_tf32(acc[mf][nf][0], acc[mf][nf][1],
                             acc[mf][nf][2], acc[mf][nf][3],
                             af[mf][0], af[mf][1], af[mf][2], af[mf][3],
                             bf[nf][0], bf[nf][1]);
        }
        __syncthreads();
    }

    // epilogue
    if (blockIdx.z == 0) {
#pragma unroll
        for (int mf = 0; mf < 4; mf++) {
#pragma unroll
            for (int nf = 0; nf < 8; nf++) {
                const int row = bm + warp_m + mf * 16 + lr;
                const int col = bn + warp_n + nf * 8 + lc * 2;
                float2 v0 = make_float2(acc[mf][nf][0], acc[mf][nf][1]);
                float2 v1 = make_float2(acc[mf][nf][2], acc[mf][nf][3]);
                *reinterpret_cast<float2*>(g_G + (size_t)row * DOUT + col) = v0;
                *reinterpret_cast<float2*>(g_G + (size_t)(row + 8) * DOUT + col) = v1;
            }
        }
    } else {
#pragma unroll
        for (int mf = 0; mf < 4; mf++) {
#pragma unroll
            for (int nf = 0; nf < 8; nf++) {
                const int row = bm + warp_m + mf * 16 + lr;
                const int col = bn + warp_n + nf * 8 + lc * 2;
                const __nv_bfloat162 h0 = __float22bfloat162_rn(
                    make_float2(acc[mf][nf][0], acc[mf][nf][1]));
                const __nv_bfloat162 h1 = __float22bfloat162_rn(
                    make_float2(acc[mf][nf][2], acc[mf][nf][3]));
                *reinterpret_cast<__nv_bfloat162*>(
                    g_Vh + (size_t)row * DOUT + col) = h0;
                *reinterpret_cast<__nv_bfloat162*>(
                    g_Vh + (size_t)(row + 8) * DOUT + col) = h1;
            }
        }
    }
}

// ===========================================================================
// Kernel 3: fused attn scores + incidence-list build.
// score = G[c1] . F[c2]  (== Q[c1].K[c2] algebraically)
// ===========================================================================
#define ATTN_BLOCKS ((NE * 32) / 256)            // 2048
#define BUILD_BLOCKS ((NE * NS + 255) / 256)     // 1024

__global__ __launch_bounds__(256) void attn_build_kernel(
    const int* __restrict__ edge_index,
    const float* __restrict__ head_weights,
    const int* __restrict__ active_heads,
    const int* __restrict__ shared_vars)
{
    if (blockIdx.x >= ATTN_BLOCKS) {
        const int idx = (blockIdx.x - ATTN_BLOCKS) * 256 + threadIdx.x;
        if (idx < NE * NS) {
            const int v = shared_vars[idx];
            const int e = idx >> 4;          // NS = 16
            const int pos = atomicAdd(&g_count[v], 1);
            if (pos < CAP) g_list[(size_t)v * CAP + pos] = e;
        }
        return;
    }

    const int e = (blockIdx.x * 256 + threadIdx.x) >> 5;
    const int lane = threadIdx.x & 31;

    const int c1 = edge_index[e];
    const int c2 = edge_index[NE + e];
    const float4* Q4 = reinterpret_cast<const float4*>(g_G + (size_t)c1 * DOUT);
    const float4* K4 = reinterpret_cast<const float4*>(g_feats + (size_t)c2 * DIN);

    float p = 0.f;
#pragma unroll
    for (int j = 0; j < 4; j++) {
        const float4 q = Q4[lane + 32 * j];
        const float4 k = K4[lane + 32 * j];
        p += q.x * k.x + q.y * k.y + q.z * k.z + q.w * k.w;
    }
#pragma unroll
    for (int off = 16; off > 0; off >>= 1)
        p += __shfl_xor_sync(0xFFFFFFFFu, p, off);

    if (lane == 0) {
        float s = p * rsqrtf((float)DOUT);
        s = (s >= 0.f) ? s : NEG_SLOPE * s;
        const float sig = 1.0f / (1.0f + __expf(-s));
        const int ah = active_heads[0];
        float hm = 0.f;
        for (int i = 0; i < ah; i++) hm += head_weights[i];
        hm /= (float)ah;
        g_attn[e] = sig * hm;
    }
}

// ===========================================================================
// Kernel 4: gather. x_out[v] = x_var[v] + sum attn[e] * Vh[c2[e]]  (bf16 V)
// ===========================================================================
__global__ __launch_bounds__(128) void gather_kernel(
    const float* __restrict__ x,
    const int* __restrict__ edge_index,
    float* __restrict__ x_out)
{
    const int v = blockIdx.x;
    const int t = threadIdx.x;

    const float4 xrow = __ldcs(
        reinterpret_cast<const float4*>(x + (size_t)v * DIN) + t);

    int cnt = g_count[v];
    if (cnt > CAP) cnt = CAP;

    __shared__ float s_a[CAP];
    __shared__ int   s_c[CAP];
    if (t < cnt) {
        const int e = g_list[(size_t)v * CAP + t];
        s_a[t] = g_attn[e];
        s_c[t] = edge_index[NE + e];
    }
    __syncthreads();
    if (t == 0) g_count[v] = 0;   // reset for next launch

    float4 acc0 = xrow;
    float4 acc1 = make_float4(0.f, 0.f, 0.f, 0.f);

    int i = 0;
    for (; i + 2 <= cnt; i += 2) {
        const float a0 = s_a[i];
        const float a1 = s_a[i + 1];
        const uint2 r0 = *reinterpret_cast<const uint2*>(
            g_Vh + (size_t)s_c[i] * DOUT + t * 4);
        const uint2 r1 = *reinterpret_cast<const uint2*>(
            g_Vh + (size_t)s_c[i + 1] * DOUT + t * 4);
        const float2 w0a = __bfloat1622float2(
            *reinterpret_cast<const __nv_bfloat162*>(&r0.x));
        const float2 w0b = __bfloat1622float2(
            *reinterpret_cast<const __nv_bfloat162*>(&r0.y));
        const float2 w1a = __bfloat1622float2(
            *reinterpret_cast<const __nv_bfloat162*>(&r1.x));
        const float2 w1b = __bfloat1622float2(
            *reinterpret_cast<const __nv_bfloat162*>(&r1.y));
        acc0.x += a0 * w0a.x; acc0.y += a0 * w0a.y;
        acc0.z += a0 * w0b.x; acc0.w += a0 * w0b.y;
        acc1.x += a1 * w1a.x; acc1.y += a1 * w1a.y;
        acc1.z += a1 * w1b.x; acc1.w += a1 * w1b.y;
    }
    if (i < cnt) {
        const float a0 = s_a[i];
        const uint2 r0 = *reinterpret_cast<const uint2*>(
            g_Vh + (size_t)s_c[i] * DOUT + t * 4);
        const float2 w0a = __bfloat1622float2(
            *reinterpret_cast<const __nv_bfloat162*>(&r0.x));
        const float2 w0b = __bfloat1622float2(
            *reinterpret_cast<const __nv_bfloat162*>(&r0.y));
        acc0.x += a0 * w0a.x; acc0.y += a0 * w0a.y;
        acc0.z += a0 * w0b.x; acc0.w += a0 * w0b.y;
    }
    acc0.x += acc1.x; acc0.y += acc1.y;
    acc0.z += acc1.z; acc0.w += acc1.w;

    __stcs(reinterpret_cast<float4*>(x_out + (size_t)v * DIN) + t, acc0);
}

// ===========================================================================
// Launch — single stream, linear graph, 5 kernels
// ===========================================================================
extern "C" void kernel_launch(void* const* d_in, const int* in_sizes, int n_in,
                              void* d_out, int out_size)
{
    const float* x_var        = (const float*)d_in[0];
    const float* W_Q          = (const float*)d_in[1];
    const float* W_K          = (const float*)d_in[2];
    const float* W_V          = (const float*)d_in[3];
    const float* head_weights = (const float*)d_in[4];
    const int*   cluster_ids  = (const int*)d_in[5];
    const int*   edge_index   = (const int*)d_in[6];
    const int*   shared_vars  = (const int*)d_in[7];
    const int*   active_heads = (const int*)d_in[8];
    float*       x_out        = (float*)d_out;

    // Mt = Wk^T * Wq  (tiny, now coalesced)
    dim3 mgrid(DOUT / 64, DIN / 64);
    mm_small_kernel<<<mgrid, 128>>>(W_K, W_Q);

    pool_kernel<<<NC, 128>>>(x_var, cluster_ids);

    dim3 ggrid(DOUT / BN, NC / BM, 2);
    gemm_tc_kernel<<<ggrid, 128>>>(W_V);

    attn_build_kernel<<<ATTN_BLOCKS + BUILD_BLOCKS, 256>>>(
        edge_index, head_weights, active_heads, shared_vars);

    gather_kernel<<<NV, 128>>>(x_var, edge_index, x_out);
}

// round 13
// speedup vs baseline: 1.2358x; 1.2274x over previous
#include <cuda_runtime.h>
#include <cuda_bf16.h>
#include <cstdint>

// Problem constants
#define NV     100000
#define DIN    512
#define DOUT   512
#define NC     4096
#define KPC    32      // vars per cluster
#define NE     16384   // edges
#define NS     16      // shared vars per edge
#define NEG_SLOPE 0.2f
#define CAP    64      // max edge contributions tracked per variable
#define GW     8       // warps (= vars) per gather block; 100000/8 = 12500

// Scratch (device globals; no allocation allowed)
__device__ float          g_feats[NC * DIN];   // 8 MB
__device__ float          g_Q[NC * DOUT];      // 8 MB
__device__ float          g_K[NC * DOUT];      // 8 MB
__device__ __nv_bfloat16  g_Vh[NC * DOUT];     // 4 MB (bf16 V for gather)
__device__ float          g_attn[NE];          // 64 KB
__device__ int            g_count[NV];         // zero-init; gather re-zeros
__device__ int            g_list[(size_t)NV * CAP]; // 25.6 MB

// ===========================================================================
// Kernel 1: per-cluster mean pooling (at DRAM roofline)
// ===========================================================================
__global__ __launch_bounds__(128) void pool_kernel(
    const float* __restrict__ x, const int* __restrict__ ids)
{
    const int c = blockIdx.x;
    const int t = threadIdx.x;
    __shared__ int s_ids[KPC];
    if (t < KPC) s_ids[t] = ids[c * KPC + t];
    __syncthreads();

    float4 acc = make_float4(0.f, 0.f, 0.f, 0.f);
#pragma unroll 4
    for (int k = 0; k < KPC; k++) {
        const float4 v = reinterpret_cast<const float4*>(
            x + (size_t)s_ids[k] * DIN)[t];
        acc.x += v.x; acc.y += v.y; acc.z += v.z; acc.w += v.w;
    }
    const float inv = 1.0f / (float)KPC;
    acc.x *= inv; acc.y *= inv; acc.z *= inv; acc.w *= inv;
    reinterpret_cast<float4*>(g_feats + (size_t)c * DIN)[t] = acc;
}

// ===========================================================================
// Kernel 2: tf32 mma.sync GEMM, 3 z-slices (R10 known-good).
// z==0: Q = F*Wq^T (fp32), z==1: K = F*Wk^T (fp32), z==2: V = F*Wv^T (bf16)
// CTA tile 128x128x32, 128 thr = 4 warps (2x2), warp tile 64x64.
// ===========================================================================
#define BM 128
#define BN 128
#define BK 32
#define SSTRIDE 36

__device__ __forceinline__ uint32_t f32_to_tf32(float f)
{
    uint32_t u;
    asm("cvt.rna.tf32.f32 %0, %1;" : "=r"(u) : "f"(f));
    return u;
}

__device__ __forceinline__ void mma_tf32(
    float& d0, float& d1, float& d2, float& d3,
    uint32_t a0, uint32_t a1, uint32_t a2, uint32_t a3,
    uint32_t b0, uint32_t b1)
{
    asm volatile(
        "mma.sync.aligned.m16n8k8.row.col.f32.tf32.tf32.f32 "
        "{%0,%1,%2,%3}, {%4,%5,%6,%7}, {%8,%9}, {%0,%1,%2,%3};"
        : "+f"(d0), "+f"(d1), "+f"(d2), "+f"(d3)
        : "r"(a0), "r"(a1), "r"(a2), "r"(a3), "r"(b0), "r"(b1));
}

__global__ __launch_bounds__(128) void gemm_tc_kernel(
    const float* __restrict__ WQ, const float* __restrict__ WK,
    const float* __restrict__ WV)
{
    __shared__ uint32_t As[BM * SSTRIDE];
    __shared__ uint32_t Bs[BN * SSTRIDE];

    const float* Bsrc;
    float* C = nullptr;
    if      (blockIdx.z == 0) { Bsrc = WQ; C = g_Q; }
    else if (blockIdx.z == 1) { Bsrc = WK; C = g_K; }
    else                      { Bsrc = WV; }
    const float* A = g_feats;

    const int tid  = threadIdx.x;
    const int wid  = tid >> 5;
    const int lane = tid & 31;
    const int bm = blockIdx.y * BM;
    const int bn = blockIdx.x * BN;

    const int warp_m = (wid >> 1) * 64;   // 0 or 64
    const int warp_n = (wid & 1) * 64;    // 0 or 64
    const int lr = lane >> 2;             // 0..7
    const int lc = lane & 3;              // 0..3

    float acc[4][8][4];
#pragma unroll
    for (int i = 0; i < 4; i++)
#pragma unroll
        for (int j = 0; j < 8; j++)
#pragma unroll
            for (int r = 0; r < 4; r++) acc[i][j][r] = 0.f;

    for (int k0 = 0; k0 < DIN; k0 += BK) {
#pragma unroll
        for (int i = 0; i < 8; i++) {
            const int q   = tid + i * 128;     // 0..1023 float4 slots
            const int row = q >> 3;            // 0..127
            const int kq  = (q & 7) * 4;       // 0..28
            const float4 a = *reinterpret_cast<const float4*>(
                A + (size_t)(bm + row) * DIN + k0 + kq);
            uint4 ua;
            ua.x = f32_to_tf32(a.x); ua.y = f32_to_tf32(a.y);
            ua.z = f32_to_tf32(a.z); ua.w = f32_to_tf32(a.w);
            *reinterpret_cast<uint4*>(&As[row * SSTRIDE + kq]) = ua;
            const float4 b = *reinterpret_cast<const float4*>(
                Bsrc + (size_t)(bn + row) * DIN + k0 + kq);
            uint4 ub;
            ub.x = f32_to_tf32(b.x); ub.y = f32_to_tf32(b.y);
            ub.z = f32_to_tf32(b.z); ub.w = f32_to_tf32(b.w);
            *reinterpret_cast<uint4*>(&Bs[row * SSTRIDE + kq]) = ub;
        }
        __syncthreads();

#pragma unroll
        for (int ks = 0; ks < 4; ks++) {
            const int kk = ks * 8;
            uint32_t af[4][4];
#pragma unroll
            for (int mf = 0; mf < 4; mf++) {
                const int rbase = (warp_m + mf * 16 + lr) * SSTRIDE + kk + lc;
                af[mf][0] = As[rbase];
                af[mf][1] = As[rbase + 8 * SSTRIDE];
                af[mf][2] = As[rbase + 4];
                af[mf][3] = As[rbase + 8 * SSTRIDE + 4];
            }
            uint32_t bf[8][2];
#pragma unroll
            for (int nf = 0; nf < 8; nf++) {
                const int rbase = (warp_n + nf * 8 + lr) * SSTRIDE + kk + lc;
                bf[nf][0] = Bs[rbase];
                bf[nf][1] = Bs[rbase + 4];
            }
#pragma unroll
            for (int mf = 0; mf < 4; mf++)
#pragma unroll
                for (int nf = 0; nf < 8; nf++)
                    mma_tf32(acc[mf][nf][0], acc[mf][nf][1],
                             acc[mf][nf][2], acc[mf][nf][3],
                             af[mf][0], af[mf][1], af[mf][2], af[mf][3],
                             bf[nf][0], bf[nf][1]);
        }
        __syncthreads();
    }

    // epilogue: frag (row = lr [+8], col = 2*lc [+1])
    if (blockIdx.z < 2) {
#pragma unroll
        for (int mf = 0; mf < 4; mf++) {
#pragma unroll
            for (int nf = 0; nf < 8; nf++) {
                const int row = bm + warp_m + mf * 16 + lr;
                const int col = bn + warp_n + nf * 8 + lc * 2;
                float2 v0 = make_float2(acc[mf][nf][0], acc[mf][nf][1]);
                float2 v1 = make_float2(acc[mf][nf][2], acc[mf][nf][3]);
                *reinterpret_cast<float2*>(C + (size_t)row * DOUT + col) = v0;
                *reinterpret_cast<float2*>(C + (size_t)(row + 8) * DOUT + col) = v1;
            }
        }
    } else {
#pragma unroll
        for (int mf = 0; mf < 4; mf++) {
#pragma unroll
            for (int nf = 0; nf < 8; nf++) {
                const int row = bm + warp_m + mf * 16 + lr;
                const int col = bn + warp_n + nf * 8 + lc * 2;
                const __nv_bfloat162 h0 = __float22bfloat162_rn(
                    make_float2(acc[mf][nf][0], acc[mf][nf][1]));
                const __nv_bfloat162 h1 = __float22bfloat162_rn(
                    make_float2(acc[mf][nf][2], acc[mf][nf][3]));
                *reinterpret_cast<__nv_bfloat162*>(
                    g_Vh + (size_t)row * DOUT + col) = h0;
                *reinterpret_cast<__nv_bfloat162*>(
                    g_Vh + (size_t)(row + 8) * DOUT + col) = h1;
            }
        }
    }
}

// ===========================================================================
// Kernel 3: fused attn scores + incidence-list build (R10 known-good).
// Blocks [0, 2048): one warp per edge -> g_attn.
// Blocks [2048, 3072): build var->edge lists (atomics).
// ===========================================================================
#define ATTN_BLOCKS ((NE * 32) / 256)            // 2048
#define BUILD_BLOCKS ((NE * NS + 255) / 256)     // 1024

__global__ __launch_bounds__(256) void attn_build_kernel(
    const int* __restrict__ edge_index,
    const float* __restrict__ head_weights,
    const int* __restrict__ active_heads,
    const int* __restrict__ shared_vars)
{
    if (blockIdx.x >= ATTN_BLOCKS) {
        const int idx = (blockIdx.x - ATTN_BLOCKS) * 256 + threadIdx.x;
        if (idx < NE * NS) {
            const int v = shared_vars[idx];
            const int e = idx >> 4;          // NS = 16
            const int pos = atomicAdd(&g_count[v], 1);
            if (pos < CAP) g_list[(size_t)v * CAP + pos] = e;
        }
        return;
    }

    const int e = (blockIdx.x * 256 + threadIdx.x) >> 5;
    const int lane = threadIdx.x & 31;

    const int c1 = edge_index[e];
    const int c2 = edge_index[NE + e];
    const float4* Q4 = reinterpret_cast<const float4*>(g_Q + (size_t)c1 * DOUT);
    const float4* K4 = reinterpret_cast<const float4*>(g_K + (size_t)c2 * DOUT);

    float p = 0.f;
#pragma unroll
    for (int j = 0; j < 4; j++) {
        const float4 q = Q4[lane + 32 * j];
        const float4 k = K4[lane + 32 * j];
        p += q.x * k.x + q.y * k.y + q.z * k.z + q.w * k.w;
    }
#pragma unroll
    for (int off = 16; off > 0; off >>= 1)
        p += __shfl_xor_sync(0xFFFFFFFFu, p, off);

    if (lane == 0) {
        float s = p * rsqrtf((float)DOUT);
        s = (s >= 0.f) ? s : NEG_SLOPE * s;
        const float sig = 1.0f / (1.0f + __expf(-s));
        const int ah = active_heads[0];
        float hm = 0.f;
        for (int i = 0; i < ah; i++) hm += head_weights[i];
        hm /= (float)ah;
        g_attn[e] = sig * hm;
    }
}

// ===========================================================================
// Kernel 4: gather, warp-per-var (R13).
// x_out[v] = x_var[v] + sum attn[e] * Vh[c2[e]]  (bf16 V)
// Lane owns cols {j*128 + lane*4 : j=0..3}. No smem, no block barriers.
// Metadata loaded lane-parallel, broadcast via shfl. Resets g_count[v].
// ===========================================================================
__global__ __launch_bounds__(32 * GW) void gather_kernel(
    const float* __restrict__ x,
    const int* __restrict__ edge_index,
    float* __restrict__ x_out)
{
    const int warp = threadIdx.x >> 5;
    const int lane = threadIdx.x & 31;
    const int v = blockIdx.x * GW + warp;   // grid*GW == NV exactly

    // stream x row in: 4 independent coalesced float4 loads
    const float4* xrow4 = reinterpret_cast<const float4*>(x + (size_t)v * DIN);
    float4 xr[4];
#pragma unroll
    for (int j = 0; j < 4; j++)
        xr[j] = __ldcs(xrow4 + j * 32 + lane);

    int cnt = g_count[v];                   // broadcast load (same addr)
    if (cnt > CAP) cnt = CAP;

    // lane-parallel metadata fetch (two batches cover CAP=64)
    float a0 = 0.f, a1 = 0.f;
    int   c0 = 0,   c1 = 0;
    if (lane < cnt) {
        const int e = g_list[(size_t)v * CAP + lane];
        a0 = g_attn[e];
        c0 = edge_index[NE + e];
    }
    if (lane + 32 < cnt) {
        const int e = g_list[(size_t)v * CAP + lane + 32];
        a1 = g_attn[e];
        c1 = edge_index[NE + e];
    }
    __syncwarp();
    if (lane == 0) g_count[v] = 0;          // reset for next launch

    for (int i = 0; i < cnt; i++) {
        const float a = (i < 32) ? __shfl_sync(0xFFFFFFFFu, a0, i)
                                 : __shfl_sync(0xFFFFFFFFu, a1, i - 32);
        const int   c = (i < 32) ? __shfl_sync(0xFFFFFFFFu, c0, i)
                                 : __shfl_sync(0xFFFFFFFFu, c1, i - 32);
        const __nv_bfloat16* vrow = g_Vh + (size_t)c * DOUT;
#pragma unroll
        for (int j = 0; j < 4; j++) {
            const uint2 r = *reinterpret_cast<const uint2*>(
                vrow + j * 128 + lane * 4);
            const float2 wa = __bfloat1622float2(
                *reinterpret_cast<const __nv_bfloat162*>(&r.x));
            const float2 wb = __bfloat1622float2(
                *reinterpret_cast<const __nv_bfloat162*>(&r.y));
            xr[j].x += a * wa.x; xr[j].y += a * wa.y;
            xr[j].z += a * wb.x; xr[j].w += a * wb.y;
        }
    }

    float4* orow4 = reinterpret_cast<float4*>(x_out + (size_t)v * DIN);
#pragma unroll
    for (int j = 0; j < 4; j++)
        __stcs(orow4 + j * 32 + lane, xr[j]);
}

// ===========================================================================
// Launch — single stream, linear graph, 4 kernels (R10 structure)
// ===========================================================================
extern "C" void kernel_launch(void* const* d_in, const int* in_sizes, int n_in,
                              void* d_out, int out_size)
{
    const float* x_var        = (const float*)d_in[0];
    const float* W_Q          = (const float*)d_in[1];
    const float* W_K          = (const float*)d_in[2];
    const float* W_V          = (const float*)d_in[3];
    const float* head_weights = (const float*)d_in[4];
    const int*   cluster_ids  = (const int*)d_in[5];
    const int*   edge_index   = (const int*)d_in[6];
    const int*   shared_vars  = (const int*)d_in[7];
    const int*   active_heads = (const int*)d_in[8];
    float*       x_out        = (float*)d_out;

    pool_kernel<<<NC, 128>>>(x_var, cluster_ids);

    dim3 ggrid(DOUT / BN, NC / BM, 3);
    gemm_tc_kernel<<<ggrid, 128>>>(W_Q, W_K, W_V);

    attn_build_kernel<<<ATTN_BLOCKS + BUILD_BLOCKS, 256>>>(
        edge_index, head_weights, active_heads, shared_vars);

    gather_kernel<<<NV / GW, 32 * GW>>>(x_var, edge_index, x_out);
}

// round 14
// speedup vs baseline: 1.3214x; 1.0692x over previous
#include <cuda_runtime.h>
#include <cuda_bf16.h>
#include <cstdint>

// Problem constants
#define NV     100000
#define DIN    512
#define DOUT   512
#define NC     4096
#define KPC    32      // vars per cluster
#define NE     16384   // edges
#define NS     16      // shared vars per edge
#define NEG_SLOPE 0.2f
#define CAP    64      // max edge contributions tracked per variable
#define GW     8       // warps (= vars) per gather block

// Scratch (device globals; no allocation allowed)
__device__ float          g_feats[NC * DIN];   // 8 MB
__device__ float          g_Q[NC * DOUT];      // 8 MB
__device__ float          g_K[NC * DOUT];      // 8 MB
__device__ __nv_bfloat16  g_Vh[NC * DOUT];     // 4 MB (bf16 V for gather)
__device__ float          g_attn[NE];          // 64 KB
__device__ int            g_count[NV];         // zero-init; gather re-zeros
__device__ int            g_list[(size_t)NV * CAP]; // 25.6 MB

// ===========================================================================
// Kernel 1: per-cluster mean pooling (at DRAM roofline)
// ===========================================================================
__global__ __launch_bounds__(128) void pool_kernel(
    const float* __restrict__ x, const int* __restrict__ ids)
{
    const int c = blockIdx.x;
    const int t = threadIdx.x;
    __shared__ int s_ids[KPC];
    if (t < KPC) s_ids[t] = ids[c * KPC + t];
    __syncthreads();

    float4 acc = make_float4(0.f, 0.f, 0.f, 0.f);
#pragma unroll 4
    for (int k = 0; k < KPC; k++) {
        const float4 v = reinterpret_cast<const float4*>(
            x + (size_t)s_ids[k] * DIN)[t];
        acc.x += v.x; acc.y += v.y; acc.z += v.z; acc.w += v.w;
    }
    const float inv = 1.0f / (float)KPC;
    acc.x *= inv; acc.y *= inv; acc.z *= inv; acc.w *= inv;
    reinterpret_cast<float4*>(g_feats + (size_t)c * DIN)[t] = acc;
}

// ===========================================================================
// Kernel 2: bf16 m16n8k16 mma.sync GEMM (R14: 2x flops/instr vs tf32 k8).
// z==0: Q = F*Wq^T (fp32), z==1: K = F*Wk^T (fp32), z==2: V = F*Wv^T (bf16)
// CTA tile 128x128x32, 128 thr = 4 warps (2x2), warp tile 64x64.
// Smem: packed bf16 pairs, 16 u32/row + pad -> stride 20 (conflict-free
// fragment loads: banks r*20+lc mod 32 distinct for r in 0..7, lc in 0..3).
// ===========================================================================
#define BM 128
#define BN 128
#define BK 32
#define SS2 20   // u32 stride per row (16 data + 4 pad)

__device__ __forceinline__ uint32_t pack_bf16(float lo, float hi)
{
    const __nv_bfloat162 h = __float22bfloat162_rn(make_float2(lo, hi));
    return *reinterpret_cast<const uint32_t*>(&h);
}

__device__ __forceinline__ void mma_bf16(
    float& d0, float& d1, float& d2, float& d3,
    uint32_t a0, uint32_t a1, uint32_t a2, uint32_t a3,
    uint32_t b0, uint32_t b1)
{
    asm volatile(
        "mma.sync.aligned.m16n8k16.row.col.f32.bf16.bf16.f32 "
        "{%0,%1,%2,%3}, {%4,%5,%6,%7}, {%8,%9}, {%0,%1,%2,%3};"
        : "+f"(d0), "+f"(d1), "+f"(d2), "+f"(d3)
        : "r"(a0), "r"(a1), "r"(a2), "r"(a3), "r"(b0), "r"(b1));
}

__global__ __launch_bounds__(128) void gemm_tc_kernel(
    const float* __restrict__ WQ, const float* __restrict__ WK,
    const float* __restrict__ WV)
{
    __shared__ uint32_t As[BM * SS2];
    __shared__ uint32_t Bs[BN * SS2];

    const float* Bsrc;
    float* C = nullptr;
    if      (blockIdx.z == 0) { Bsrc = WQ; C = g_Q; }
    else if (blockIdx.z == 1) { Bsrc = WK; C = g_K; }
    else                      { Bsrc = WV; }
    const float* A = g_feats;

    const int tid  = threadIdx.x;
    const int wid  = tid >> 5;
    const int lane = tid & 31;
    const int bm = blockIdx.y * BM;
    const int bn = blockIdx.x * BN;

    const int warp_m = (wid >> 1) * 64;   // 0 or 64
    const int warp_n = (wid & 1) * 64;    // 0 or 64
    const int lr = lane >> 2;             // 0..7
    const int lc = lane & 3;              // 0..3

    float acc[4][8][4];
#pragma unroll
    for (int i = 0; i < 4; i++)
#pragma unroll
        for (int j = 0; j < 8; j++)
#pragma unroll
            for (int r = 0; r < 4; r++) acc[i][j][r] = 0.f;

    for (int k0 = 0; k0 < DIN; k0 += BK) {
        // ---- stage global fp32 -> packed bf16 pairs in smem ----
#pragma unroll
        for (int i = 0; i < 8; i++) {
            const int q   = tid + i * 128;     // 0..1023 float4 slots
            const int row = q >> 3;            // 0..127
            const int kq  = (q & 7) * 4;       // fp32 col offset 0..28
            const int p   = (q & 7) * 2;       // packed-u32 col 0..14
            const float4 a = *reinterpret_cast<const float4*>(
                A + (size_t)(bm + row) * DIN + k0 + kq);
            uint2 ua;
            ua.x = pack_bf16(a.x, a.y);
            ua.y = pack_bf16(a.z, a.w);
            *reinterpret_cast<uint2*>(&As[row * SS2 + p]) = ua;
            const float4 b = *reinterpret_cast<const float4*>(
                Bsrc + (size_t)(bn + row) * DIN + k0 + kq);
            uint2 ub;
            ub.x = pack_bf16(b.x, b.y);
            ub.y = pack_bf16(b.z, b.w);
            *reinterpret_cast<uint2*>(&Bs[row * SS2 + p]) = ub;
        }
        __syncthreads();

        // ---- compute 2 k16-steps ----
#pragma unroll
        for (int ks = 0; ks < 2; ks++) {
            const int kk = ks * 8;             // packed-u32 col base
            uint32_t af[4][4];
#pragma unroll
            for (int mf = 0; mf < 4; mf++) {
                const int rbase = (warp_m + mf * 16 + lr) * SS2 + kk + lc;
                af[mf][0] = As[rbase];                 // (m=lr,   k=2lc..)
                af[mf][1] = As[rbase + 8 * SS2];       // (m=lr+8, k=2lc..)
                af[mf][2] = As[rbase + 4];             // (m=lr,   k=2lc+8..)
                af[mf][3] = As[rbase + 8 * SS2 + 4];   // (m=lr+8, k=2lc+8..)
            }
            uint32_t bf[8][2];
#pragma unroll
            for (int nf = 0; nf < 8; nf++) {
                const int rbase = (warp_n + nf * 8 + lr) * SS2 + kk + lc;
                bf[nf][0] = Bs[rbase];                 // (n=lr, k=2lc..)
                bf[nf][1] = Bs[rbase + 4];             // (n=lr, k=2lc+8..)
            }
#pragma unroll
            for (int mf = 0; mf < 4; mf++)
#pragma unroll
                for (int nf = 0; nf < 8; nf++)
                    mma_bf16(acc[mf][nf][0], acc[mf][nf][1],
                             acc[mf][nf][2], acc[mf][nf][3],
                             af[mf][0], af[mf][1], af[mf][2], af[mf][3],
                             bf[nf][0], bf[nf][1]);
        }
        __syncthreads();
    }

    // epilogue: frag (row = lr [+8], col = 2*lc [+1])
    if (blockIdx.z < 2) {
#pragma unroll
        for (int mf = 0; mf < 4; mf++) {
#pragma unroll
            for (int nf = 0; nf < 8; nf++) {
                const int row = bm + warp_m + mf * 16 + lr;
                const int col = bn + warp_n + nf * 8 + lc * 2;
                float2 v0 = make_float2(acc[mf][nf][0], acc[mf][nf][1]);
                float2 v1 = make_float2(acc[mf][nf][2], acc[mf][nf][3]);
                *reinterpret_cast<float2*>(C + (size_t)row * DOUT + col) = v0;
                *reinterpret_cast<float2*>(C + (size_t)(row + 8) * DOUT + col) = v1;
            }
        }
    } else {
#pragma unroll
        for (int mf = 0; mf < 4; mf++) {
#pragma unroll
            for (int nf = 0; nf < 8; nf++) {
                const int row = bm + warp_m + mf * 16 + lr;
                const int col = bn + warp_n + nf * 8 + lc * 2;
                const __nv_bfloat162 h0 = __float22bfloat162_rn(
                    make_float2(acc[mf][nf][0], acc[mf][nf][1]));
                const __nv_bfloat162 h1 = __float22bfloat162_rn(
                    make_float2(acc[mf][nf][2], acc[mf][nf][3]));
                *reinterpret_cast<__nv_bfloat162*>(
                    g_Vh + (size_t)row * DOUT + col) = h0;
                *reinterpret_cast<__nv_bfloat162*>(
                    g_Vh + (size_t)(row + 8) * DOUT + col) = h1;
            }
        }
    }
}

// ===========================================================================
// Kernel 3: fused attn scores + incidence-list build.
// ===========================================================================
#define ATTN_BLOCKS ((NE * 32) / 256)            // 2048
#define BUILD_BLOCKS ((NE * NS + 255) / 256)     // 1024

__global__ __launch_bounds__(256) void attn_build_kernel(
    const int* __restrict__ edge_index,
    const float* __restrict__ head_weights,
    const int* __restrict__ active_heads,
    const int* __restrict__ shared_vars)
{
    if (blockIdx.x >= ATTN_BLOCKS) {
        const int idx = (blockIdx.x - ATTN_BLOCKS) * 256 + threadIdx.x;
        if (idx < NE * NS) {
            const int v = shared_vars[idx];
            const int e = idx >> 4;          // NS = 16
            const int pos = atomicAdd(&g_count[v], 1);
            if (pos < CAP) g_list[(size_t)v * CAP + pos] = e;
        }
        return;
    }

    const int e = (blockIdx.x * 256 + threadIdx.x) >> 5;
    const int lane = threadIdx.x & 31;

    const int c1 = edge_index[e];
    const int c2 = edge_index[NE + e];
    const float4* Q4 = reinterpret_cast<const float4*>(g_Q + (size_t)c1 * DOUT);
    const float4* K4 = reinterpret_cast<const float4*>(g_K + (size_t)c2 * DOUT);

    float p = 0.f;
#pragma unroll
    for (int j = 0; j < 4; j++) {
        const float4 q = Q4[lane + 32 * j];
        const float4 k = K4[lane + 32 * j];
        p += q.x * k.x + q.y * k.y + q.z * k.z + q.w * k.w;
    }
#pragma unroll
    for (int off = 16; off > 0; off >>= 1)
        p += __shfl_xor_sync(0xFFFFFFFFu, p, off);

    if (lane == 0) {
        float s = p * rsqrtf((float)DOUT);
        s = (s >= 0.f) ? s : NEG_SLOPE * s;
        const float sig = 1.0f / (1.0f + __expf(-s));
        const int ah = active_heads[0];
        float hm = 0.f;
        for (int i = 0; i < ah; i++) hm += head_weights[i];
        hm /= (float)ah;
        g_attn[e] = sig * hm;
    }
}

// ===========================================================================
// Kernel 4: gather, warp-per-var (R13 known-good).
// x_out[v] = x_var[v] + sum attn[e] * Vh[c2[e]]  (bf16 V)
// ===========================================================================
__global__ __launch_bounds__(32 * GW) void gather_kernel(
    const float* __restrict__ x,
    const int* __restrict__ edge_index,
    float* __restrict__ x_out)
{
    const int warp = threadIdx.x >> 5;
    const int lane = threadIdx.x & 31;
    const int v = blockIdx.x * GW + warp;   // grid*GW == NV exactly

    const float4* xrow4 = reinterpret_cast<const float4*>(x + (size_t)v * DIN);
    float4 xr[4];
#pragma unroll
    for (int j = 0; j < 4; j++)
        xr[j] = __ldcs(xrow4 + j * 32 + lane);

    int cnt = g_count[v];
    if (cnt > CAP) cnt = CAP;

    float a0 = 0.f, a1 = 0.f;
    int   c0 = 0,   c1 = 0;
    if (lane < cnt) {
        const int e = g_list[(size_t)v * CAP + lane];
        a0 = g_attn[e];
        c0 = edge_index[NE + e];
    }
    if (lane + 32 < cnt) {
        const int e = g_list[(size_t)v * CAP + lane + 32];
        a1 = g_attn[e];
        c1 = edge_index[NE + e];
    }
    __syncwarp();
    if (lane == 0) g_count[v] = 0;          // reset for next launch

    for (int i = 0; i < cnt; i++) {
        const float a = (i < 32) ? __shfl_sync(0xFFFFFFFFu, a0, i)
                                 : __shfl_sync(0xFFFFFFFFu, a1, i - 32);
        const int   c = (i < 32) ? __shfl_sync(0xFFFFFFFFu, c0, i)
                                 : __shfl_sync(0xFFFFFFFFu, c1, i - 32);
        const __nv_bfloat16* vrow = g_Vh + (size_t)c * DOUT;
#pragma unroll
        for (int j = 0; j < 4; j++) {
            const uint2 r = *reinterpret_cast<const uint2*>(
                vrow + j * 128 + lane * 4);
            const float2 wa = __bfloat1622float2(
                *reinterpret_cast<const __nv_bfloat162*>(&r.x));
            const float2 wb = __bfloat1622float2(
                *reinterpret_cast<const __nv_bfloat162*>(&r.y));
            xr[j].x += a * wa.x; xr[j].y += a * wa.y;
            xr[j].z += a * wb.x; xr[j].w += a * wb.y;
        }
    }

    float4* orow4 = reinterpret_cast<float4*>(x_out + (size_t)v * DIN);
#pragma unroll
    for (int j = 0; j < 4; j++)
        __stcs(orow4 + j * 32 + lane, xr[j]);
}

// ===========================================================================
// Launch — single stream, linear graph, 4 kernels
// ===========================================================================
extern "C" void kernel_launch(void* const* d_in, const int* in_sizes, int n_in,
                              void* d_out, int out_size)
{
    const float* x_var        = (const float*)d_in[0];
    const float* W_Q          = (const float*)d_in[1];
    const float* W_K          = (const float*)d_in[2];
    const float* W_V          = (const float*)d_in[3];
    const float* head_weights = (const float*)d_in[4];
    const int*   cluster_ids  = (const int*)d_in[5];
    const int*   edge_index   = (const int*)d_in[6];
    const int*   shared_vars  = (const int*)d_in[7];
    const int*   active_heads = (const int*)d_in[8];
    float*       x_out        = (float*)d_out;

    pool_kernel<<<NC, 128>>>(x_var, cluster_ids);

    dim3 ggrid(DOUT / BN, NC / BM, 3);
    gemm_tc_kernel<<<ggrid, 128>>>(W_Q, W_K, W_V);

    attn_build_kernel<<<ATTN_BLOCKS + BUILD_BLOCKS, 256>>>(
        edge_index, head_weights, active_heads, shared_vars);

    gather_kernel<<<NV / GW, 32 * GW>>>(x_var, edge_index, x_out);
}

// round 15
// speedup vs baseline: 1.3623x; 1.0309x over previous
#include <cuda_runtime.h>
#include <cuda_bf16.h>
#include <cstdint>

// Problem constants
#define NV     100000
#define DIN    512
#define DOUT   512
#define NC     4096
#define KPC    32      // vars per cluster
#define NE     16384   // edges
#define NS     16      // shared vars per edge
#define NEG_SLOPE 0.2f
#define CAP    64      // max edge contributions tracked per variable
#define GW     8       // warps (= vars) per gather block

// Scratch (device globals; no allocation allowed)
__device__ float          g_feats[NC * DIN];   // 8 MB
__device__ __nv_bfloat16  g_Qh[NC * DOUT];     // 4 MB (bf16 Q)
__device__ __nv_bfloat16  g_Kh[NC * DOUT];     // 4 MB (bf16 K)
__device__ __nv_bfloat16  g_Vh[NC * DOUT];     // 4 MB (bf16 V)
__device__ float          g_attn[NE];          // 64 KB
__device__ int            g_count[NV];         // zero-init; gather re-zeros
__device__ int            g_list[(size_t)NV * CAP]; // 25.6 MB

// ===========================================================================
// Kernel 1: per-cluster mean pooling + (fused) incidence-list build.
// Blocks [0, NC): pooling (DRAM-bound).  Blocks [NC, NC+2048): list build
// (atomics hide under the pool phase's DRAM traffic).
// ===========================================================================
#define POOL_BUILD_BLOCKS ((NE * NS) / 128)   // 2048

__global__ __launch_bounds__(128) void pool_build_kernel(
    const float* __restrict__ x, const int* __restrict__ ids,
    const int* __restrict__ shared_vars)
{
    if (blockIdx.x >= NC) {
        const int idx = (blockIdx.x - NC) * 128 + threadIdx.x;  // < NE*NS
        const int v = shared_vars[idx];
        const int e = idx >> 4;          // NS = 16
        const int pos = atomicAdd(&g_count[v], 1);
        if (pos < CAP) g_list[(size_t)v * CAP + pos] = e;
        return;
    }

    const int c = blockIdx.x;
    const int t = threadIdx.x;
    __shared__ int s_ids[KPC];
    if (t < KPC) s_ids[t] = ids[c * KPC + t];
    __syncthreads();

    float4 acc = make_float4(0.f, 0.f, 0.f, 0.f);
#pragma unroll 4
    for (int k = 0; k < KPC; k++) {
        const float4 v = reinterpret_cast<const float4*>(
            x + (size_t)s_ids[k] * DIN)[t];
        acc.x += v.x; acc.y += v.y; acc.z += v.z; acc.w += v.w;
    }
    const float inv = 1.0f / (float)KPC;
    acc.x *= inv; acc.y *= inv; acc.z *= inv; acc.w *= inv;
    reinterpret_cast<float4*>(g_feats + (size_t)c * DIN)[t] = acc;
}

// ===========================================================================
// Kernel 2: bf16 m16n8k16 mma.sync GEMM (R14 mainloop, uniform bf16 out).
// z==0: Q, z==1: K, z==2: V  — all bf16 to g_Qh/g_Kh/g_Vh.
// CTA tile 128x128x32, 128 thr = 4 warps (2x2), warp tile 64x64.
// ===========================================================================
#define BM 128
#define BN 128
#define BK 32
#define SS2 20   // u32 stride per row (16 data + 4 pad)

__device__ __forceinline__ uint32_t pack_bf16(float lo, float hi)
{
    const __nv_bfloat162 h = __float22bfloat162_rn(make_float2(lo, hi));
    return *reinterpret_cast<const uint32_t*>(&h);
}

__device__ __forceinline__ void mma_bf16(
    float& d0, float& d1, float& d2, float& d3,
    uint32_t a0, uint32_t a1, uint32_t a2, uint32_t a3,
    uint32_t b0, uint32_t b1)
{
    asm volatile(
        "mma.sync.aligned.m16n8k16.row.col.f32.bf16.bf16.f32 "
        "{%0,%1,%2,%3}, {%4,%5,%6,%7}, {%8,%9}, {%0,%1,%2,%3};"
        : "+f"(d0), "+f"(d1), "+f"(d2), "+f"(d3)
        : "r"(a0), "r"(a1), "r"(a2), "r"(a3), "r"(b0), "r"(b1));
}

__global__ __launch_bounds__(128) void gemm_tc_kernel(
    const float* __restrict__ WQ, const float* __restrict__ WK,
    const float* __restrict__ WV)
{
    __shared__ uint32_t As[BM * SS2];
    __shared__ uint32_t Bs[BN * SS2];

    const float* Bsrc;
    __nv_bfloat16* C;
    if      (blockIdx.z == 0) { Bsrc = WQ; C = g_Qh; }
    else if (blockIdx.z == 1) { Bsrc = WK; C = g_Kh; }
    else                      { Bsrc = WV; C = g_Vh; }
    const float* A = g_feats;

    const int tid  = threadIdx.x;
    const int wid  = tid >> 5;
    const int lane = tid & 31;
    const int bm = blockIdx.y * BM;
    const int bn = blockIdx.x * BN;

    const int warp_m = (wid >> 1) * 64;   // 0 or 64
    const int warp_n = (wid & 1) * 64;    // 0 or 64
    const int lr = lane >> 2;             // 0..7
    const int lc = lane & 3;              // 0..3

    float acc[4][8][4];
#pragma unroll
    for (int i = 0; i < 4; i++)
#pragma unroll
        for (int j = 0; j < 8; j++)
#pragma unroll
            for (int r = 0; r < 4; r++) acc[i][j][r] = 0.f;

    for (int k0 = 0; k0 < DIN; k0 += BK) {
        // ---- stage global fp32 -> packed bf16 pairs in smem ----
#pragma unroll
        for (int i = 0; i < 8; i++) {
            const int q   = tid + i * 128;     // 0..1023 float4 slots
            const int row = q >> 3;            // 0..127
            const int kq  = (q & 7) * 4;       // fp32 col offset 0..28
            const int p   = (q & 7) * 2;       // packed-u32 col 0..14
            const float4 a = *reinterpret_cast<const float4*>(
                A + (size_t)(bm + row) * DIN + k0 + kq);
            uint2 ua;
            ua.x = pack_bf16(a.x, a.y);
            ua.y = pack_bf16(a.z, a.w);
            *reinterpret_cast<uint2*>(&As[row * SS2 + p]) = ua;
            const float4 b = *reinterpret_cast<const float4*>(
                Bsrc + (size_t)(bn + row) * DIN + k0 + kq);
            uint2 ub;
            ub.x = pack_bf16(b.x, b.y);
            ub.y = pack_bf16(b.z, b.w);
            *reinterpret_cast<uint2*>(&Bs[row * SS2 + p]) = ub;
        }
        __syncthreads();

        // ---- compute 2 k16-steps ----
#pragma unroll
        for (int ks = 0; ks < 2; ks++) {
            const int kk = ks * 8;             // packed-u32 col base
            uint32_t af[4][4];
#pragma unroll
            for (int mf = 0; mf < 4; mf++) {
                const int rbase = (warp_m + mf * 16 + lr) * SS2 + kk + lc;
                af[mf][0] = As[rbase];
                af[mf][1] = As[rbase + 8 * SS2];
                af[mf][2] = As[rbase + 4];
                af[mf][3] = As[rbase + 8 * SS2 + 4];
            }
            uint32_t bf[8][2];
#pragma unroll
            for (int nf = 0; nf < 8; nf++) {
                const int rbase = (warp_n + nf * 8 + lr) * SS2 + kk + lc;
                bf[nf][0] = Bs[rbase];
                bf[nf][1] = Bs[rbase + 4];
            }
#pragma unroll
            for (int mf = 0; mf < 4; mf++)
#pragma unroll
                for (int nf = 0; nf < 8; nf++)
                    mma_bf16(acc[mf][nf][0], acc[mf][nf][1],
                             acc[mf][nf][2], acc[mf][nf][3],
                             af[mf][0], af[mf][1], af[mf][2], af[mf][3],
                             bf[nf][0], bf[nf][1]);
        }
        __syncthreads();
    }

    // epilogue: uniform bf16 stores, frag (row = lr [+8], col = 2*lc [+1])
#pragma unroll
    for (int mf = 0; mf < 4; mf++) {
#pragma unroll
        for (int nf = 0; nf < 8; nf++) {
            const int row = bm + warp_m + mf * 16 + lr;
            const int col = bn + warp_n + nf * 8 + lc * 2;
            const __nv_bfloat162 h0 = __float22bfloat162_rn(
                make_float2(acc[mf][nf][0], acc[mf][nf][1]));
            const __nv_bfloat162 h1 = __float22bfloat162_rn(
                make_float2(acc[mf][nf][2], acc[mf][nf][3]));
            *reinterpret_cast<__nv_bfloat162*>(
                C + (size_t)row * DOUT + col) = h0;
            *reinterpret_cast<__nv_bfloat162*>(
                C + (size_t)(row + 8) * DOUT + col) = h1;
        }
    }
}

// ===========================================================================
// Kernel 3: attn scores, one warp per edge; bf16 Q/K (half the L2 traffic).
// ===========================================================================
#define ATTN_BLOCKS ((NE * 32) / 256)            // 2048

__device__ __forceinline__ float dot8_bf16(uint4 q, uint4 k)
{
    float p = 0.f;
    const uint32_t* qa = &q.x;
    const uint32_t* ka = &k.x;
#pragma unroll
    for (int i = 0; i < 4; i++) {
        const float2 qf = __bfloat1622float2(
            *reinterpret_cast<const __nv_bfloat162*>(&qa[i]));
        const float2 kf = __bfloat1622float2(
            *reinterpret_cast<const __nv_bfloat162*>(&ka[i]));
        p += qf.x * kf.x + qf.y * kf.y;
    }
    return p;
}

__global__ __launch_bounds__(256) void attn_kernel(
    const int* __restrict__ edge_index,
    const float* __restrict__ head_weights,
    const int* __restrict__ active_heads)
{
    const int e = (blockIdx.x * 256 + threadIdx.x) >> 5;
    const int lane = threadIdx.x & 31;

    const int c1 = edge_index[e];
    const int c2 = edge_index[NE + e];
    const __nv_bfloat16* Qr = g_Qh + (size_t)c1 * DOUT;
    const __nv_bfloat16* Kr = g_Kh + (size_t)c2 * DOUT;

    float p = 0.f;
#pragma unroll
    for (int j = 0; j < 2; j++) {
        const uint4 q = *reinterpret_cast<const uint4*>(Qr + j * 256 + lane * 8);
        const uint4 k = *reinterpret_cast<const uint4*>(Kr + j * 256 + lane * 8);
        p += dot8_bf16(q, k);
    }
#pragma unroll
    for (int off = 16; off > 0; off >>= 1)
        p += __shfl_xor_sync(0xFFFFFFFFu, p, off);

    if (lane == 0) {
        float s = p * rsqrtf((float)DOUT);
        s = (s >= 0.f) ? s : NEG_SLOPE * s;
        const float sig = 1.0f / (1.0f + __expf(-s));
        const int ah = active_heads[0];
        float hm = 0.f;
        for (int i = 0; i < ah; i++) hm += head_weights[i];
        hm /= (float)ah;
        g_attn[e] = sig * hm;
    }
}

// ===========================================================================
// Kernel 4: gather, warp-per-var (R13 known-good).
// x_out[v] = x_var[v] + sum attn[e] * Vh[c2[e]]  (bf16 V)
// ===========================================================================
__global__ __launch_bounds__(32 * GW) void gather_kernel(
    const float* __restrict__ x,
    const int* __restrict__ edge_index,
    float* __restrict__ x_out)
{
    const int warp = threadIdx.x >> 5;
    const int lane = threadIdx.x & 31;
    const int v = blockIdx.x * GW + warp;   // grid*GW == NV exactly

    const float4* xrow4 = reinterpret_cast<const float4*>(x + (size_t)v * DIN);
    float4 xr[4];
#pragma unroll
    for (int j = 0; j < 4; j++)
        xr[j] = __ldcs(xrow4 + j * 32 + lane);

    int cnt = g_count[v];
    if (cnt > CAP) cnt = CAP;

    float a0 = 0.f, a1 = 0.f;
    int   c0 = 0,   c1 = 0;
    if (lane < cnt) {
        const int e = g_list[(size_t)v * CAP + lane];
        a0 = g_attn[e];
        c0 = edge_index[NE + e];
    }
    if (lane + 32 < cnt) {
        const int e = g_list[(size_t)v * CAP + lane + 32];
        a1 = g_attn[e];
        c1 = edge_index[NE + e];
    }
    __syncwarp();
    if (lane == 0) g_count[v] = 0;          // reset for next launch

    for (int i = 0; i < cnt; i++) {
        const float a = (i < 32) ? __shfl_sync(0xFFFFFFFFu, a0, i)
                                 : __shfl_sync(0xFFFFFFFFu, a1, i - 32);
        const int   c = (i < 32) ? __shfl_sync(0xFFFFFFFFu, c0, i)
                                 : __shfl_sync(0xFFFFFFFFu, c1, i - 32);
        const __nv_bfloat16* vrow = g_Vh + (size_t)c * DOUT;
#pragma unroll
        for (int j = 0; j < 4; j++) {
            const uint2 r = *reinterpret_cast<const uint2*>(
                vrow + j * 128 + lane * 4);
            const float2 wa = __bfloat1622float2(
                *reinterpret_cast<const __nv_bfloat162*>(&r.x));
            const float2 wb = __bfloat1622float2(
                *reinterpret_cast<const __nv_bfloat162*>(&r.y));
            xr[j].x += a * wa.x; xr[j].y += a * wa.y;
            xr[j].z += a * wb.x; xr[j].w += a * wb.y;
        }
    }

    float4* orow4 = reinterpret_cast<float4*>(x_out + (size_t)v * DIN);
#pragma unroll
    for (int j = 0; j < 4; j++)
        __stcs(orow4 + j * 32 + lane, xr[j]);
}

// ===========================================================================
// Launch — single stream, linear graph, 4 kernels
// ===========================================================================
extern "C" void kernel_launch(void* const* d_in, const int* in_sizes, int n_in,
                              void* d_out, int out_size)
{
    const float* x_var        = (const float*)d_in[0];
    const float* W_Q          = (const float*)d_in[1];
    const float* W_K          = (const float*)d_in[2];
    const float* W_V          = (const float*)d_in[3];
    const float* head_weights = (const float*)d_in[4];
    const int*   cluster_ids  = (const int*)d_in[5];
    const int*   edge_index   = (const int*)d_in[6];
    const int*   shared_vars  = (const int*)d_in[7];
    const int*   active_heads = (const int*)d_in[8];
    float*       x_out        = (float*)d_out;

    pool_build_kernel<<<NC + POOL_BUILD_BLOCKS, 128>>>(
        x_var, cluster_ids, shared_vars);

    dim3 ggrid(DOUT / BN, NC / BM, 3);
    gemm_tc_kernel<<<ggrid, 128>>>(W_Q, W_K, W_V);

    attn_kernel<<<ATTN_BLOCKS, 256>>>(edge_index, head_weights, active_heads);

    gather_kernel<<<NV / GW, 32 * GW>>>(x_var, edge_index, x_out);
}

// round 16
// speedup vs baseline: 1.5278x; 1.1215x over previous
#include <cuda_runtime.h>
#include <cuda_bf16.h>
#include <cstdint>

// Problem constants
#define NV     100000
#define DIN    512
#define DOUT   512
#define NC     4096
#define KPC    32      // vars per cluster
#define NE     16384   // edges
#define NS     16      // shared vars per edge
#define NEG_SLOPE 0.2f
#define CAP    64      // max edge contributions tracked per variable
#define GW     8       // warps (= vars) per gather block

// Scratch (device globals; no allocation allowed)
__device__ __nv_bfloat16  g_featsh[NC * DIN];  // 4 MB (bf16 pooled feats)
__device__ __nv_bfloat16  g_Wh[3 * DOUT * DIN]; // 1.5 MB (bf16 Wq|Wk|Wv)
__device__ __nv_bfloat16  g_Qh[NC * DOUT];     // 4 MB (bf16 Q)
__device__ __nv_bfloat16  g_Kh[NC * DOUT];     // 4 MB (bf16 K)
__device__ __nv_bfloat16  g_Vh[NC * DOUT];     // 4 MB (bf16 V)
__device__ float          g_attn[NE];          // 64 KB
__device__ int            g_count[NV];         // zero-init; gather re-zeros
__device__ int            g_list[(size_t)NV * CAP]; // 25.6 MB

__device__ __forceinline__ uint32_t pack_bf16(float lo, float hi)
{
    const __nv_bfloat162 h = __float22bfloat162_rn(make_float2(lo, hi));
    return *reinterpret_cast<const uint32_t*>(&h);
}

// ===========================================================================
// Kernel 1: fused pooling + incidence-list build + W->bf16 conversion.
// Blocks [0, NC):                pooling (DRAM-bound), bf16 output
// Blocks [NC, NC+2048):          var->edge list build (atomics)
// Blocks [NC+2048, NC+2048+1536): W fp32->bf16 (hides under pool DRAM phase)
// ===========================================================================
#define BUILD_BLOCKS ((NE * NS) / 128)            // 2048
#define WELEMS (DOUT * DIN)                        // 262144 per matrix
#define WCONV_BLOCKS ((3 * WELEMS) / (128 * 4))    // 1536

__global__ __launch_bounds__(128) void pool_build_kernel(
    const float* __restrict__ x, const int* __restrict__ ids,
    const int* __restrict__ shared_vars,
    const float* __restrict__ Wq, const float* __restrict__ Wk,
    const float* __restrict__ Wv)
{
    if (blockIdx.x >= NC + BUILD_BLOCKS) {
        // ---- W conversion branch ----
        const int g = (blockIdx.x - NC - BUILD_BLOCKS) * 128 + threadIdx.x;
        const int z   = g / (WELEMS / 4);          // matrix id
        const int off = (g % (WELEMS / 4)) * 4;    // float offset
        const float* W = (z == 0) ? Wq : (z == 1) ? Wk : Wv;
        const float4 w = *reinterpret_cast<const float4*>(W + off);
        uint2 u;
        u.x = pack_bf16(w.x, w.y);
        u.y = pack_bf16(w.z, w.w);
        *reinterpret_cast<uint2*>(g_Wh + (size_t)z * WELEMS + off) = u;
        return;
    }
    if (blockIdx.x >= NC) {
        // ---- incidence-list build branch ----
        const int idx = (blockIdx.x - NC) * 128 + threadIdx.x;  // < NE*NS
        const int v = shared_vars[idx];
        const int e = idx >> 4;          // NS = 16
        const int pos = atomicAdd(&g_count[v], 1);
        if (pos < CAP) g_list[(size_t)v * CAP + pos] = e;
        return;
    }

    // ---- pooling branch ----
    const int c = blockIdx.x;
    const int t = threadIdx.x;
    __shared__ int s_ids[KPC];
    if (t < KPC) s_ids[t] = ids[c * KPC + t];
    __syncthreads();

    float4 acc = make_float4(0.f, 0.f, 0.f, 0.f);
#pragma unroll 4
    for (int k = 0; k < KPC; k++) {
        const float4 v = reinterpret_cast<const float4*>(
            x + (size_t)s_ids[k] * DIN)[t];
        acc.x += v.x; acc.y += v.y; acc.z += v.z; acc.w += v.w;
    }
    const float inv = 1.0f / (float)KPC;
    uint2 o;
    o.x = pack_bf16(acc.x * inv, acc.y * inv);
    o.y = pack_bf16(acc.z * inv, acc.w * inv);
    *reinterpret_cast<uint2*>(g_featsh + (size_t)c * DIN + t * 4) = o;
}

// ===========================================================================
// Kernel 2: bf16 m16n8k16 mma.sync GEMM — pure-copy staging (operands
// pre-converted to bf16; identical rounding to the old in-loop cvt).
// z==0: Q, z==1: K, z==2: V  — bf16 out to g_Qh/g_Kh/g_Vh.
// CTA tile 128x128x32, 128 thr = 4 warps (2x2), warp tile 64x64.
// ===========================================================================
#define BM 128
#define BN 128
#define BK 32
#define SS2 20   // u32 stride per row (16 data + 4 pad)

__device__ __forceinline__ void mma_bf16(
    float& d0, float& d1, float& d2, float& d3,
    uint32_t a0, uint32_t a1, uint32_t a2, uint32_t a3,
    uint32_t b0, uint32_t b1)
{
    asm volatile(
        "mma.sync.aligned.m16n8k16.row.col.f32.bf16.bf16.f32 "
        "{%0,%1,%2,%3}, {%4,%5,%6,%7}, {%8,%9}, {%0,%1,%2,%3};"
        : "+f"(d0), "+f"(d1), "+f"(d2), "+f"(d3)
        : "r"(a0), "r"(a1), "r"(a2), "r"(a3), "r"(b0), "r"(b1));
}

__global__ __launch_bounds__(128) void gemm_tc_kernel()
{
    __shared__ uint32_t As[BM * SS2];
    __shared__ uint32_t Bs[BN * SS2];

    const __nv_bfloat16* Ah = g_featsh;
    const __nv_bfloat16* Bh = g_Wh + (size_t)blockIdx.z * WELEMS;
    __nv_bfloat16* C;
    if      (blockIdx.z == 0) C = g_Qh;
    else if (blockIdx.z == 1) C = g_Kh;
    else                      C = g_Vh;

    const int tid  = threadIdx.x;
    const int wid  = tid >> 5;
    const int lane = tid & 31;
    const int bm = blockIdx.y * BM;
    const int bn = blockIdx.x * BN;

    const int warp_m = (wid >> 1) * 64;   // 0 or 64
    const int warp_n = (wid & 1) * 64;    // 0 or 64
    const int lr = lane >> 2;             // 0..7
    const int lc = lane & 3;              // 0..3

    float acc[4][8][4];
#pragma unroll
    for (int i = 0; i < 4; i++)
#pragma unroll
        for (int j = 0; j < 8; j++)
#pragma unroll
            for (int r = 0; r < 4; r++) acc[i][j][r] = 0.f;

    for (int k0 = 0; k0 < DIN; k0 += BK) {
        // ---- stage: straight bf16 copy (no conversion) ----
#pragma unroll
        for (int i = 0; i < 8; i++) {
            const int q   = tid + i * 128;     // 0..1023 uint2 slots
            const int row = q >> 3;            // 0..127
            const int p   = (q & 7) * 2;       // packed-u32 col 0..14
            const uint2 ua = *reinterpret_cast<const uint2*>(
                Ah + (size_t)(bm + row) * DIN + k0 + p * 2);
            *reinterpret_cast<uint2*>(&As[row * SS2 + p]) = ua;
            const uint2 ub = *reinterpret_cast<const uint2*>(
                Bh + (size_t)(bn + row) * DIN + k0 + p * 2);
            *reinterpret_cast<uint2*>(&Bs[row * SS2 + p]) = ub;
        }
        __syncthreads();

        // ---- compute 2 k16-steps ----
#pragma unroll
        for (int ks = 0; ks < 2; ks++) {
            const int kk = ks * 8;             // packed-u32 col base
            uint32_t af[4][4];
#pragma unroll
            for (int mf = 0; mf < 4; mf++) {
                const int rbase = (warp_m + mf * 16 + lr) * SS2 + kk + lc;
                af[mf][0] = As[rbase];
                af[mf][1] = As[rbase + 8 * SS2];
                af[mf][2] = As[rbase + 4];
                af[mf][3] = As[rbase + 8 * SS2 + 4];
            }
            uint32_t bf[8][2];
#pragma unroll
            for (int nf = 0; nf < 8; nf++) {
                const int rbase = (warp_n + nf * 8 + lr) * SS2 + kk + lc;
                bf[nf][0] = Bs[rbase];
                bf[nf][1] = Bs[rbase + 4];
            }
#pragma unroll
            for (int mf = 0; mf < 4; mf++)
#pragma unroll
                for (int nf = 0; nf < 8; nf++)
                    mma_bf16(acc[mf][nf][0], acc[mf][nf][1],
                             acc[mf][nf][2], acc[mf][nf][3],
                             af[mf][0], af[mf][1], af[mf][2], af[mf][3],
                             bf[nf][0], bf[nf][1]);
        }
        __syncthreads();
    }

    // epilogue: bf16 stores, frag (row = lr [+8], col = 2*lc [+1])
#pragma unroll
    for (int mf = 0; mf < 4; mf++) {
#pragma unroll
        for (int nf = 0; nf < 8; nf++) {
            const int row = bm + warp_m + mf * 16 + lr;
            const int col = bn + warp_n + nf * 8 + lc * 2;
            const __nv_bfloat162 h0 = __float22bfloat162_rn(
                make_float2(acc[mf][nf][0], acc[mf][nf][1]));
            const __nv_bfloat162 h1 = __float22bfloat162_rn(
                make_float2(acc[mf][nf][2], acc[mf][nf][3]));
            *reinterpret_cast<__nv_bfloat162*>(
                C + (size_t)row * DOUT + col) = h0;
            *reinterpret_cast<__nv_bfloat162*>(
                C + (size_t)(row + 8) * DOUT + col) = h1;
        }
    }
}

// ===========================================================================
// Kernel 3: attn scores, one warp per edge; bf16 Q/K.
// ===========================================================================
#define ATTN_BLOCKS ((NE * 32) / 256)            // 2048

__device__ __forceinline__ float dot8_bf16(uint4 q, uint4 k)
{
    float p = 0.f;
    const uint32_t* qa = &q.x;
    const uint32_t* ka = &k.x;
#pragma unroll
    for (int i = 0; i < 4; i++) {
        const float2 qf = __bfloat1622float2(
            *reinterpret_cast<const __nv_bfloat162*>(&qa[i]));
        const float2 kf = __bfloat1622float2(
            *reinterpret_cast<const __nv_bfloat162*>(&ka[i]));
        p += qf.x * kf.x + qf.y * kf.y;
    }
    return p;
}

__global__ __launch_bounds__(256) void attn_kernel(
    const int* __restrict__ edge_index,
    const float* __restrict__ head_weights,
    const int* __restrict__ active_heads)
{
    const int e = (blockIdx.x * 256 + threadIdx.x) >> 5;
    const int lane = threadIdx.x & 31;

    const int c1 = edge_index[e];
    const int c2 = edge_index[NE + e];
    const __nv_bfloat16* Qr = g_Qh + (size_t)c1 * DOUT;
    const __nv_bfloat16* Kr = g_Kh + (size_t)c2 * DOUT;

    float p = 0.f;
#pragma unroll
    for (int j = 0; j < 2; j++) {
        const uint4 q = *reinterpret_cast<const uint4*>(Qr + j * 256 + lane * 8);
        const uint4 k = *reinterpret_cast<const uint4*>(Kr + j * 256 + lane * 8);
        p += dot8_bf16(q, k);
    }
#pragma unroll
    for (int off = 16; off > 0; off >>= 1)
        p += __shfl_xor_sync(0xFFFFFFFFu, p, off);

    if (lane == 0) {
        float s = p * rsqrtf((float)DOUT);
        s = (s >= 0.f) ? s : NEG_SLOPE * s;
        const float sig = 1.0f / (1.0f + __expf(-s));
        const int ah = active_heads[0];
        float hm = 0.f;
        for (int i = 0; i < ah; i++) hm += head_weights[i];
        hm /= (float)ah;
        g_attn[e] = sig * hm;
    }
}

// ===========================================================================
// Kernel 4: gather, warp-per-var (known-good).
// x_out[v] = x_var[v] + sum attn[e] * Vh[c2[e]]  (bf16 V)
// ===========================================================================
__global__ __launch_bounds__(32 * GW) void gather_kernel(
    const float* __restrict__ x,
    const int* __restrict__ edge_index,
    float* __restrict__ x_out)
{
    const int warp = threadIdx.x >> 5;
    const int lane = threadIdx.x & 31;
    const int v = blockIdx.x * GW + warp;   // grid*GW == NV exactly

    const float4* xrow4 = reinterpret_cast<const float4*>(x + (size_t)v * DIN);
    float4 xr[4];
#pragma unroll
    for (int j = 0; j < 4; j++)
        xr[j] = __ldcs(xrow4 + j * 32 + lane);

    int cnt = g_count[v];
    if (cnt > CAP) cnt = CAP;

    float a0 = 0.f, a1 = 0.f;
    int   c0 = 0,   c1 = 0;
    if (lane < cnt) {
        const int e = g_list[(size_t)v * CAP + lane];
        a0 = g_attn[e];
        c0 = edge_index[NE + e];
    }
    if (lane + 32 < cnt) {
        const int e = g_list[(size_t)v * CAP + lane + 32];
        a1 = g_attn[e];
        c1 = edge_index[NE + e];
    }
    __syncwarp();
    if (lane == 0) g_count[v] = 0;          // reset for next launch

    for (int i = 0; i < cnt; i++) {
        const float a = (i < 32) ? __shfl_sync(0xFFFFFFFFu, a0, i)
                                 : __shfl_sync(0xFFFFFFFFu, a1, i - 32);
        const int   c = (i < 32) ? __shfl_sync(0xFFFFFFFFu, c0, i)
                                 : __shfl_sync(0xFFFFFFFFu, c1, i - 32);
        const __nv_bfloat16* vrow = g_Vh + (size_t)c * DOUT;
#pragma unroll
        for (int j = 0; j < 4; j++) {
            const uint2 r = *reinterpret_cast<const uint2*>(
                vrow + j * 128 + lane * 4);
            const float2 wa = __bfloat1622float2(
                *reinterpret_cast<const __nv_bfloat162*>(&r.x));
            const float2 wb = __bfloat1622float2(
                *reinterpret_cast<const __nv_bfloat162*>(&r.y));
            xr[j].x += a * wa.x; xr[j].y += a * wa.y;
            xr[j].z += a * wb.x; xr[j].w += a * wb.y;
        }
    }

    float4* orow4 = reinterpret_cast<float4*>(x_out + (size_t)v * DIN);
#pragma unroll
    for (int j = 0; j < 4; j++)
        __stcs(orow4 + j * 32 + lane, xr[j]);
}

// ===========================================================================
// Launch — single stream, linear graph, 4 kernels
// ===========================================================================
extern "C" void kernel_launch(void* const* d_in, const int* in_sizes, int n_in,
                              void* d_out, int out_size)
{
    const float* x_var        = (const float*)d_in[0];
    const float* W_Q          = (const float*)d_in[1];
    const float* W_K          = (const float*)d_in[2];
    const float* W_V          = (const float*)d_in[3];
    const float* head_weights = (const float*)d_in[4];
    const int*   cluster_ids  = (const int*)d_in[5];
    const int*   edge_index   = (const int*)d_in[6];
    const int*   shared_vars  = (const int*)d_in[7];
    const int*   active_heads = (const int*)d_in[8];
    float*       x_out        = (float*)d_out;

    pool_build_kernel<<<NC + BUILD_BLOCKS + WCONV_BLOCKS, 128>>>(
        x_var, cluster_ids, shared_vars, W_Q, W_K, W_V);

    dim3 ggrid(DOUT / BN, NC / BM, 3);
    gemm_tc_kernel<<<ggrid, 128>>>();

    attn_kernel<<<ATTN_BLOCKS, 256>>>(edge_index, head_weights, active_heads);

    gather_kernel<<<NV / GW, 32 * GW>>>(x_var, edge_index, x_out);
}

// round 17
// speedup vs baseline: 1.5891x; 1.0402x over previous
#include <cuda_runtime.h>
#include <cuda_bf16.h>
#include <cstdint>

// Problem constants
#define NV     100000
#define DIN    512
#define DOUT   512
#define NC     4096
#define KPC    32      // vars per cluster
#define NE     16384   // edges
#define NS     16      // shared vars per edge
#define NEG_SLOPE 0.2f
#define CAP    64      // max edge contributions tracked per variable
#define GW     8       // warps (= vars) per gather block

// Scratch (device globals; no allocation allowed)
__device__ __nv_bfloat16  g_featsh[NC * DIN];   // 4 MB (bf16 pooled feats)
__device__ __nv_bfloat16  g_Wh[3 * DOUT * DIN]; // 1.5 MB (bf16 Wq|Wk|Wv)
__device__ __nv_bfloat16  g_Qh[NC * DOUT];      // 4 MB
__device__ __nv_bfloat16  g_Kh[NC * DOUT];      // 4 MB
__device__ __nv_bfloat16  g_Vh[NC * DOUT];      // 4 MB
__device__ float          g_attn[NE];           // 64 KB
__device__ int            g_count[NV];          // zero-init; gather re-zeros
__device__ int            g_list[(size_t)NV * CAP]; // 25.6 MB

__device__ __forceinline__ uint32_t pack_bf16(float lo, float hi)
{
    const __nv_bfloat162 h = __float22bfloat162_rn(make_float2(lo, hi));
    return *reinterpret_cast<const uint32_t*>(&h);
}

// ===========================================================================
// Kernel 1: fused pooling + incidence-list build + W->bf16 conversion.
// Blocks [0, NC): pooling.  [NC, NC+2048): list build.  [.., +1536): W conv.
// ===========================================================================
#define BUILD_BLOCKS ((NE * NS) / 128)            // 2048
#define WELEMS (DOUT * DIN)                        // 262144 per matrix
#define WCONV_BLOCKS ((3 * WELEMS) / (128 * 4))    // 1536

__global__ __launch_bounds__(128) void pool_build_kernel(
    const float* __restrict__ x, const int* __restrict__ ids,
    const int* __restrict__ shared_vars,
    const float* __restrict__ Wq, const float* __restrict__ Wk,
    const float* __restrict__ Wv)
{
    if (blockIdx.x >= NC + BUILD_BLOCKS) {
        // ---- W conversion branch ----
        const int g = (blockIdx.x - NC - BUILD_BLOCKS) * 128 + threadIdx.x;
        const int z   = g / (WELEMS / 4);          // matrix id
        const int off = (g % (WELEMS / 4)) * 4;    // float offset
        const float* W = (z == 0) ? Wq : (z == 1) ? Wk : Wv;
        const float4 w = *reinterpret_cast<const float4*>(W + off);
        uint2 u;
        u.x = pack_bf16(w.x, w.y);
        u.y = pack_bf16(w.z, w.w);
        *reinterpret_cast<uint2*>(g_Wh + (size_t)z * WELEMS + off) = u;
        return;
    }
    if (blockIdx.x >= NC) {
        // ---- incidence-list build branch ----
        const int idx = (blockIdx.x - NC) * 128 + threadIdx.x;  // < NE*NS
        const int v = shared_vars[idx];
        const int e = idx >> 4;          // NS = 16
        const int pos = atomicAdd(&g_count[v], 1);
        if (pos < CAP) g_list[(size_t)v * CAP + pos] = e;
        return;
    }

    // ---- pooling branch ----
    const int c = blockIdx.x;
    const int t = threadIdx.x;
    __shared__ int s_ids[KPC];
    if (t < KPC) s_ids[t] = ids[c * KPC + t];
    __syncthreads();

    float4 acc = make_float4(0.f, 0.f, 0.f, 0.f);
#pragma unroll 4
    for (int k = 0; k < KPC; k++) {
        const float4 v = reinterpret_cast<const float4*>(
            x + (size_t)s_ids[k] * DIN)[t];
        acc.x += v.x; acc.y += v.y; acc.z += v.z; acc.w += v.w;
    }
    const float inv = 1.0f / (float)KPC;
    uint2 o;
    o.x = pack_bf16(acc.x * inv, acc.y * inv);
    o.y = pack_bf16(acc.z * inv, acc.w * inv);
    *reinterpret_cast<uint2*>(g_featsh + (size_t)c * DIN + t * 4) = o;
}

// ===========================================================================
// Kernel 2: bf16 m16n8k16 GEMM — BK=64 chunks (R17), uint4 staging.
// z==0: Q, z==1: K, z==2: V  — bf16 out to g_Qh/g_Kh/g_Vh.
// CTA tile 128x128x64, 128 thr = 4 warps (2x2), warp tile 64x64.
// Smem row: 32 data u32 + pad -> stride 36 (frag banks 4r+lc distinct).
// ===========================================================================
#define BM 128
#define BN 128
#define BK 64
#define SS2 36   // u32 stride per row (32 data + 4 pad)

__device__ __forceinline__ void mma_bf16(
    float& d0, float& d1, float& d2, float& d3,
    uint32_t a0, uint32_t a1, uint32_t a2, uint32_t a3,
    uint32_t b0, uint32_t b1)
{
    asm volatile(
        "mma.sync.aligned.m16n8k16.row.col.f32.bf16.bf16.f32 "
        "{%0,%1,%2,%3}, {%4,%5,%6,%7}, {%8,%9}, {%0,%1,%2,%3};"
        : "+f"(d0), "+f"(d1), "+f"(d2), "+f"(d3)
        : "r"(a0), "r"(a1), "r"(a2), "r"(a3), "r"(b0), "r"(b1));
}

__global__ __launch_bounds__(128) void gemm_tc_kernel()
{
    __shared__ uint32_t As[BM * SS2];
    __shared__ uint32_t Bs[BN * SS2];

    const __nv_bfloat16* Ah = g_featsh;
    const __nv_bfloat16* Bh = g_Wh + (size_t)blockIdx.z * WELEMS;
    __nv_bfloat16* C;
    if      (blockIdx.z == 0) C = g_Qh;
    else if (blockIdx.z == 1) C = g_Kh;
    else                      C = g_Vh;

    const int tid  = threadIdx.x;
    const int wid  = tid >> 5;
    const int lane = tid & 31;
    const int bm = blockIdx.y * BM;
    const int bn = blockIdx.x * BN;

    const int warp_m = (wid >> 1) * 64;   // 0 or 64
    const int warp_n = (wid & 1) * 64;    // 0 or 64
    const int lr = lane >> 2;             // 0..7
    const int lc = lane & 3;              // 0..3

    float acc[4][8][4];
#pragma unroll
    for (int i = 0; i < 4; i++)
#pragma unroll
        for (int j = 0; j < 8; j++)
#pragma unroll
            for (int r = 0; r < 4; r++) acc[i][j][r] = 0.f;

    for (int k0 = 0; k0 < DIN; k0 += BK) {
        // ---- stage: uint4 bf16 copy (8 loads/thread/matrix) ----
#pragma unroll
        for (int i = 0; i < 8; i++) {
            const int q   = tid + i * 128;     // 0..1023 uint4 slots
            const int row = q >> 3;            // 0..127
            const int p   = (q & 7) * 4;       // packed-u32 col 0..28
            const uint4 ua = *reinterpret_cast<const uint4*>(
                Ah + (size_t)row * DIN + k0 + p * 2 + (size_t)bm * DIN);
            *reinterpret_cast<uint4*>(&As[row * SS2 + p]) = ua;
            const uint4 ub = *reinterpret_cast<const uint4*>(
                Bh + (size_t)row * DIN + k0 + p * 2 + (size_t)bn * DIN);
            *reinterpret_cast<uint4*>(&Bs[row * SS2 + p]) = ub;
        }
        __syncthreads();

        // ---- compute 4 k16-steps ----
#pragma unroll
        for (int ks = 0; ks < 4; ks++) {
            const int kk = ks * 8;             // packed-u32 col base
            uint32_t af[4][4];
#pragma unroll
            for (int mf = 0; mf < 4; mf++) {
                const int rbase = (warp_m + mf * 16 + lr) * SS2 + kk + lc;
                af[mf][0] = As[rbase];
                af[mf][1] = As[rbase + 8 * SS2];
                af[mf][2] = As[rbase + 4];
                af[mf][3] = As[rbase + 8 * SS2 + 4];
            }
            uint32_t bf[8][2];
#pragma unroll
            for (int nf = 0; nf < 8; nf++) {
                const int rbase = (warp_n + nf * 8 + lr) * SS2 + kk + lc;
                bf[nf][0] = Bs[rbase];
                bf[nf][1] = Bs[rbase + 4];
            }
#pragma unroll
            for (int mf = 0; mf < 4; mf++)
#pragma unroll
                for (int nf = 0; nf < 8; nf++)
                    mma_bf16(acc[mf][nf][0], acc[mf][nf][1],
                             acc[mf][nf][2], acc[mf][nf][3],
                             af[mf][0], af[mf][1], af[mf][2], af[mf][3],
                             bf[nf][0], bf[nf][1]);
        }
        __syncthreads();
    }

    // epilogue: bf16 stores, frag (row = lr [+8], col = 2*lc [+1])
#pragma unroll
    for (int mf = 0; mf < 4; mf++) {
#pragma unroll
        for (int nf = 0; nf < 8; nf++) {
            const int row = bm + warp_m + mf * 16 + lr;
            const int col = bn + warp_n + nf * 8 + lc * 2;
            const __nv_bfloat162 h0 = __float22bfloat162_rn(
                make_float2(acc[mf][nf][0], acc[mf][nf][1]));
            const __nv_bfloat162 h1 = __float22bfloat162_rn(
                make_float2(acc[mf][nf][2], acc[mf][nf][3]));
            *reinterpret_cast<__nv_bfloat162*>(
                C + (size_t)row * DOUT + col) = h0;
            *reinterpret_cast<__nv_bfloat162*>(
                C + (size_t)(row + 8) * DOUT + col) = h1;
        }
    }
}

// ===========================================================================
// Kernel 3: attn scores, one warp per edge; bf16 Q/K.
// ===========================================================================
#define ATTN_BLOCKS ((NE * 32) / 256)            // 2048

__device__ __forceinline__ float dot8_bf16(uint4 q, uint4 k)
{
    float p = 0.f;
    const uint32_t* qa = &q.x;
    const uint32_t* ka = &k.x;
#pragma unroll
    for (int i = 0; i < 4; i++) {
        const float2 qf = __bfloat1622float2(
            *reinterpret_cast<const __nv_bfloat162*>(&qa[i]));
        const float2 kf = __bfloat1622float2(
            *reinterpret_cast<const __nv_bfloat162*>(&ka[i]));
        p += qf.x * kf.x + qf.y * kf.y;
    }
    return p;
}

__global__ __launch_bounds__(256) void attn_kernel(
    const int* __restrict__ edge_index,
    const float* __restrict__ head_weights,
    const int* __restrict__ active_heads)
{
    const int e = (blockIdx.x * 256 + threadIdx.x) >> 5;
    const int lane = threadIdx.x & 31;

    const int c1 = edge_index[e];
    const int c2 = edge_index[NE + e];
    const __nv_bfloat16* Qr = g_Qh + (size_t)c1 * DOUT;
    const __nv_bfloat16* Kr = g_Kh + (size_t)c2 * DOUT;

    float p = 0.f;
#pragma unroll
    for (int j = 0; j < 2; j++) {
        const uint4 q = *reinterpret_cast<const uint4*>(Qr + j * 256 + lane * 8);
        const uint4 k = *reinterpret_cast<const uint4*>(Kr + j * 256 + lane * 8);
        p += dot8_bf16(q, k);
    }
#pragma unroll
    for (int off = 16; off > 0; off >>= 1)
        p += __shfl_xor_sync(0xFFFFFFFFu, p, off);

    if (lane == 0) {
        float s = p * rsqrtf((float)DOUT);
        s = (s >= 0.f) ? s : NEG_SLOPE * s;
        const float sig = 1.0f / (1.0f + __expf(-s));
        const int ah = active_heads[0];
        float hm = 0.f;
        for (int i = 0; i < ah; i++) hm += head_weights[i];
        hm /= (float)ah;
        g_attn[e] = sig * hm;
    }
}

// ===========================================================================
// Kernel 4: gather, warp-per-var (at DRAM roofline — frozen).
// x_out[v] = x_var[v] + sum attn[e] * Vh[c2[e]]  (bf16 V)
// ===========================================================================
__global__ __launch_bounds__(32 * GW) void gather_kernel(
    const float* __restrict__ x,
    const int* __restrict__ edge_index,
    float* __restrict__ x_out)
{
    const int warp = threadIdx.x >> 5;
    const int lane = threadIdx.x & 31;
    const int v = blockIdx.x * GW + warp;   // grid*GW == NV exactly

    const float4* xrow4 = reinterpret_cast<const float4*>(x + (size_t)v * DIN);
    float4 xr[4];
#pragma unroll
    for (int j = 0; j < 4; j++)
        xr[j] = __ldcs(xrow4 + j * 32 + lane);

    int cnt = g_count[v];
    if (cnt > CAP) cnt = CAP;

    float a0 = 0.f, a1 = 0.f;
    int   c0 = 0,   c1 = 0;
    if (lane < cnt) {
        const int e = g_list[(size_t)v * CAP + lane];
        a0 = g_attn[e];
        c0 = edge_index[NE + e];
    }
    if (lane + 32 < cnt) {
        const int e = g_list[(size_t)v * CAP + lane + 32];
        a1 = g_attn[e];
        c1 = edge_index[NE + e];
    }
    __syncwarp();
    if (lane == 0) g_count[v] = 0;          // reset for next launch

    for (int i = 0; i < cnt; i++) {
        const float a = (i < 32) ? __shfl_sync(0xFFFFFFFFu, a0, i)
                                 : __shfl_sync(0xFFFFFFFFu, a1, i - 32);
        const int   c = (i < 32) ? __shfl_sync(0xFFFFFFFFu, c0, i)
                                 : __shfl_sync(0xFFFFFFFFu, c1, i - 32);
        const __nv_bfloat16* vrow = g_Vh + (size_t)c * DOUT;
#pragma unroll
        for (int j = 0; j < 4; j++) {
            const uint2 r = *reinterpret_cast<const uint2*>(
                vrow + j * 128 + lane * 4);
            const float2 wa = __bfloat1622float2(
                *reinterpret_cast<const __nv_bfloat162*>(&r.x));
            const float2 wb = __bfloat1622float2(
                *reinterpret_cast<const __nv_bfloat162*>(&r.y));
            xr[j].x += a * wa.x; xr[j].y += a * wa.y;
            xr[j].z += a * wb.x; xr[j].w += a * wb.y;
        }
    }

    float4* orow4 = reinterpret_cast<float4*>(x_out + (size_t)v * DIN);
#pragma unroll
    for (int j = 0; j < 4; j++)
        __stcs(orow4 + j * 32 + lane, xr[j]);
}

// ===========================================================================
// Launch — single stream, linear graph, 4 kernels
// ===========================================================================
extern "C" void kernel_launch(void* const* d_in, const int* in_sizes, int n_in,
                              void* d_out, int out_size)
{
    const float* x_var        = (const float*)d_in[0];
    const float* W_Q          = (const float*)d_in[1];
    const float* W_K          = (const float*)d_in[2];
    const float* W_V          = (const float*)d_in[3];
    const float* head_weights = (const float*)d_in[4];
    const int*   cluster_ids  = (const int*)d_in[5];
    const int*   edge_index   = (const int*)d_in[6];
    const int*   shared_vars  = (const int*)d_in[7];
    const int*   active_heads = (const int*)d_in[8];
    float*       x_out        = (float*)d_out;

    pool_build_kernel<<<NC + BUILD_BLOCKS + WCONV_BLOCKS, 128>>>(
        x_var, cluster_ids, shared_vars, W_Q, W_K, W_V);

    dim3 ggrid(DOUT / BN, NC / BM, 3);
    gemm_tc_kernel<<<ggrid, 128>>>();

    attn_kernel<<<ATTN_BLOCKS, 256>>>(edge_index, head_weights, active_heads);

    gather_kernel<<<NV / GW, 32 * GW>>>(x_var, edge_index, x_out);
}